// round 2
// baseline (speedup 1.0000x reference)
#include <cuda_runtime.h>
#include <cuda_bf16.h>

#define N_NODES 100000
#define N_EDGES 1600000
#define D 128

#define GEMM_ROWS   64
#define GEMM_BLOCKS ((N_NODES + GEMM_ROWS - 1) / GEMM_ROWS)   // 1563
#define COUNT_BLOCKS ((N_EDGES + 255) / 256)                  // 6250

// ---------------- static device scratch ----------------
__device__ float g_h[(size_t)N_NODES * D];   // x @ W
__device__ float g_dis[N_NODES];             // deg^{-1/2}
__device__ int   g_deg[N_NODES];
__device__ int   g_rowptr[N_NODES + 1];
__device__ int   g_cursor[N_NODES];
__device__ int   g_col[N_EDGES];
#define SCAN_B 1024
#define N_SCAN_BLOCKS ((N_NODES + SCAN_B - 1) / SCAN_B)   // 98
__device__ int   g_bsums[N_SCAN_BLOCKS];

// ---------------- f32x2 packed-FMA helpers ----------------
__device__ __forceinline__ unsigned long long pack2(float a, float b) {
    unsigned long long u;
    asm("mov.b64 %0, {%1, %2};" : "=l"(u) : "f"(a), "f"(b));
    return u;
}
#define FMA2(d, a, b, c) \
    asm("fma.rn.f32x2 %0, %1, %2, %3;" : "=l"(d) : "l"(a), "l"(b), "l"(c))

// ---------------- kernels ----------------

__global__ void k_init_deg() {
    int i = blockIdx.x * blockDim.x + threadIdx.x;
    if (i < N_NODES) g_deg[i] = 0;
}

// Fused: blocks [0, GEMM_BLOCKS) compute h = x @ W with packed f32x2 FMA;
// blocks [GEMM_BLOCKS, ...) count in-degrees (independent work, overlapped).
__global__ void __launch_bounds__(256) k_gemm_count(const float* __restrict__ x,
                                                    const float* __restrict__ W,
                                                    const int* __restrict__ dst) {
    extern __shared__ unsigned long long sm[];          // ws: 8192 u64 (64KB), xs: 32KB
    unsigned long long* ws = sm;
    float* xs = (float*)(sm + 8192);

    if (blockIdx.x >= GEMM_BLOCKS) {
        int e = (blockIdx.x - GEMM_BLOCKS) * 256 + threadIdx.x;
        if (e < N_EDGES) atomicAdd(&g_deg[dst[e]], 1);
        return;
    }

    int row0 = blockIdx.x * GEMM_ROWS;
    // stage W (128x128 f32 = 64KB) into smem
    {
        const ulonglong2* Wg = (const ulonglong2*)W;
        ulonglong2* wsv = (ulonglong2*)ws;
        #pragma unroll
        for (int i = threadIdx.x; i < (D * D) / 4; i += 256)   // 4096
            wsv[i] = Wg[i];
    }
    // stage 64 x-rows (32KB)
    {
        const float4* xg = (const float4*)x;
        float4* xsv = (float4*)xs;
        #pragma unroll
        for (int i = threadIdx.x; i < GEMM_ROWS * 32; i += 256) {
            int r = row0 + (i >> 5);
            xsv[i] = (r < N_NODES) ? xg[(size_t)r * 32 + (i & 31)]
                                   : make_float4(0.f, 0.f, 0.f, 0.f);
        }
    }
    __syncthreads();

    int jg = threadIdx.x & 15;   // 16 col-groups of 8 cols (4 f32x2 pairs)
    int rg = threadIdx.x >> 4;   // 16 row-groups of 4 rows
    unsigned long long acc[4][4];
    #pragma unroll
    for (int r = 0; r < 4; r++)
        #pragma unroll
        for (int i = 0; i < 4; i++) acc[r][i] = 0ull;

    const ulonglong2* wsv2 = (const ulonglong2*)ws;
    #pragma unroll 4
    for (int k = 0; k < D; k++) {
        ulonglong2 wa = wsv2[k * 32 + jg * 2];
        ulonglong2 wb = wsv2[k * 32 + jg * 2 + 1];
        #pragma unroll
        for (int r = 0; r < 4; r++) {
            float xv = xs[((rg << 2) + r) * D + k];
            unsigned long long xx = pack2(xv, xv);
            FMA2(acc[r][0], xx, wa.x, acc[r][0]);
            FMA2(acc[r][1], xx, wa.y, acc[r][1]);
            FMA2(acc[r][2], xx, wb.x, acc[r][2]);
            FMA2(acc[r][3], xx, wb.y, acc[r][3]);
        }
    }

    ulonglong2* hv = (ulonglong2*)g_h;
    #pragma unroll
    for (int r = 0; r < 4; r++) {
        int row = row0 + (rg << 2) + r;
        if (row < N_NODES) {
            ulonglong2 t0; t0.x = acc[r][0]; t0.y = acc[r][1];
            ulonglong2 t1; t1.x = acc[r][2]; t1.y = acc[r][3];
            hv[(size_t)row * 32 + jg * 2]     = t0;
            hv[(size_t)row * 32 + jg * 2 + 1] = t1;
        }
    }
}

// per-block scan of deg -> local-exclusive rowptr + block sums; also dis = rsqrt(deg+1)
__global__ void k_scan1() {
    __shared__ int s[SCAN_B];
    int tid = threadIdx.x;
    int gid = blockIdx.x * SCAN_B + tid;
    int v = (gid < N_NODES) ? g_deg[gid] : 0;
    if (gid < N_NODES) g_dis[gid] = rsqrtf((float)(v + 1));
    s[tid] = v;
    __syncthreads();
    #pragma unroll
    for (int off = 1; off < SCAN_B; off <<= 1) {
        int t = (tid >= off) ? s[tid - off] : 0;
        __syncthreads();
        s[tid] += t;
        __syncthreads();
    }
    if (gid < N_NODES) g_rowptr[gid] = s[tid] - v;
    if (tid == SCAN_B - 1) g_bsums[blockIdx.x] = s[tid];
}

// each block computes its own prefix over g_bsums (98 ints) and offsets its rows
__global__ void k_scan3() {
    __shared__ int s_off;
    if (threadIdx.x == 0) s_off = 0;
    __syncthreads();
    for (int t = threadIdx.x; t < blockIdx.x; t += blockDim.x)
        atomicAdd(&s_off, g_bsums[t]);
    __syncthreads();
    int off = s_off;
    int gid = blockIdx.x * SCAN_B + threadIdx.x;
    if (gid < N_NODES) {
        int r = g_rowptr[gid] + off;
        g_rowptr[gid] = r;
        g_cursor[gid] = r;
    }
    if (blockIdx.x == 0 && threadIdx.x == 0) g_rowptr[N_NODES] = N_EDGES;
}

__global__ void k_scatter(const int* __restrict__ src, const int* __restrict__ dst) {
    int e = blockIdx.x * blockDim.x + threadIdx.x;
    if (e < N_EDGES) {
        int d = dst[e];
        int pos = atomicAdd(&g_cursor[d], 1);
        g_col[pos] = src[e];
    }
}

// one warp per node; col/dis prefetched across lanes + shfl broadcast
__global__ void __launch_bounds__(256) k_agg(const float* __restrict__ b,
                                             float* __restrict__ out) {
    int node = blockIdx.x * 8 + (threadIdx.x >> 5);
    int lane = threadIdx.x & 31;
    if (node >= N_NODES) return;

    const float4* h4 = (const float4*)g_h;
    float di = g_dis[node];
    float4 hv = h4[(size_t)node * 32 + lane];
    float4 acc;
    acc.x = di * hv.x; acc.y = di * hv.y; acc.z = di * hv.z; acc.w = di * hv.w;

    int beg = g_rowptr[node];
    int cnt = g_rowptr[node + 1] - beg;

    for (int base = 0; base < cnt; base += 32) {
        int myi = base + lane;
        int sc = 0; float ns = 0.f;
        if (myi < cnt) {
            sc = __ldg(&g_col[beg + myi]);
            ns = __ldg(&g_dis[sc]);
        }
        int m = min(32, cnt - base);
        for (int t = 0; t < m; t++) {
            int   s  = __shfl_sync(0xffffffffu, sc, t);
            float nn = __shfl_sync(0xffffffffu, ns, t);
            float4 v = __ldg(&h4[(size_t)s * 32 + lane]);
            acc.x = fmaf(nn, v.x, acc.x);
            acc.y = fmaf(nn, v.y, acc.y);
            acc.z = fmaf(nn, v.z, acc.z);
            acc.w = fmaf(nn, v.w, acc.w);
        }
    }

    float4 bv = __ldg(&((const float4*)b)[lane]);
    float4 o;
    o.x = fmaxf(fmaf(di, acc.x, bv.x), 0.f);
    o.y = fmaxf(fmaf(di, acc.y, bv.y), 0.f);
    o.z = fmaxf(fmaf(di, acc.z, bv.z), 0.f);
    o.w = fmaxf(fmaf(di, acc.w, bv.w), 0.f);
    ((float4*)out)[(size_t)node * 32 + lane] = o;
}

// ---------------- launch ----------------
extern "C" void kernel_launch(void* const* d_in, const int* in_sizes, int n_in,
                              void* d_out, int out_size) {
    const float* x   = (const float*)d_in[0];
    const int*   ei  = (const int*)d_in[1];
    const float* W   = (const float*)d_in[2];
    const float* b   = (const float*)d_in[3];
    float* out = (float*)d_out;

    const int* src = ei;
    const int* dst = ei + N_EDGES;

    const int SMEM = 96 * 1024;
    cudaFuncSetAttribute(k_gemm_count, cudaFuncAttributeMaxDynamicSharedMemorySize, SMEM);

    const int TPB = 256;
    int gN = (N_NODES + TPB - 1) / TPB;

    k_init_deg<<<gN, TPB>>>();
    k_gemm_count<<<GEMM_BLOCKS + COUNT_BLOCKS, 256, SMEM>>>(x, W, dst);
    k_scan1<<<N_SCAN_BLOCKS, SCAN_B>>>();
    k_scan3<<<N_SCAN_BLOCKS, SCAN_B>>>();
    k_scatter<<<(N_EDGES + TPB - 1) / TPB, TPB>>>(src, dst);
    k_agg<<<(N_NODES + 7) / 8, 256>>>(b, out);
}

// round 3
// speedup vs baseline: 1.3869x; 1.3869x over previous
#include <cuda_runtime.h>
#include <cuda_bf16.h>

#define N_NODES 100000
#define N_EDGES 1600000
#define D 128

#define GEMM_ROWS   64
#define GEMM_BLOCKS ((N_NODES + GEMM_ROWS - 1) / GEMM_ROWS)   // 1563

// ---------------- static device scratch ----------------
__device__ float g_h[(size_t)N_NODES * D];   // x @ W
__device__ float g_dis[N_NODES];             // deg^{-1/2}
__device__ int   g_deg[N_NODES];             // zero at load; re-zeroed by k_scan3
__device__ int   g_rowptr[N_NODES + 1];
__device__ int   g_cursor[N_NODES];
__device__ int   g_col[N_EDGES];
#define SCAN_B 1024
#define N_SCAN_BLOCKS ((N_NODES + SCAN_B - 1) / SCAN_B)   // 98
__device__ int   g_bsums[N_SCAN_BLOCKS];

// ---------------- f32x2 packed-FMA helpers ----------------
__device__ __forceinline__ unsigned long long pack2(float a) {
    unsigned long long u;
    asm("mov.b64 %0, {%1, %1};" : "=l"(u) : "f"(a));
    return u;
}
#define FMA2(d, a, b) \
    asm("fma.rn.f32x2 %0, %1, %2, %0;" : "+l"(d) : "l"(a), "l"(b))

// ---------------- GEMM (+ inline degree count) ----------------
// Block: 256 threads, 64 rows. W (64KB) + x-rows (32KB) in smem = 96KB.
// Thread (jq = t&31, rg = t>>5): cols 4*jq..4*jq+3, rows rg*8..rg*8+7.
// Warp-uniform x reads (broadcast), conflict-free float4 W reads.
// Each block also counts 1024 edge in-degrees (fire-and-forget atomics that
// drain in the shadow of the FMA loop).
__global__ void __launch_bounds__(256) k_gemm_count(const float* __restrict__ x,
                                                    const float* __restrict__ W,
                                                    const int* __restrict__ dst) {
    extern __shared__ float sm[];
    float* ws = sm;                 // W: 128*128 floats (64KB)
    float* xs = sm + D * D;         // x: 64*128 floats (32KB)

    // ---- inline degree count: fire-and-forget ----
    {
        int e0 = (blockIdx.x * 256 + threadIdx.x) * 4;
        if (e0 + 3 < N_EDGES) {
            int4 d4 = *(const int4*)(dst + e0);
            atomicAdd(&g_deg[d4.x], 1);
            atomicAdd(&g_deg[d4.y], 1);
            atomicAdd(&g_deg[d4.z], 1);
            atomicAdd(&g_deg[d4.w], 1);
        } else {
            for (int i = 0; i < 4; i++)
                if (e0 + i < N_EDGES) atomicAdd(&g_deg[dst[e0 + i]], 1);
        }
    }

    int row0 = blockIdx.x * GEMM_ROWS;
    // stage W
    {
        const float4* Wg = (const float4*)W;
        float4* wsv = (float4*)ws;
        #pragma unroll
        for (int i = threadIdx.x; i < (D * D) / 4; i += 256)
            wsv[i] = Wg[i];
    }
    // stage 64 x-rows
    {
        const float4* xg = (const float4*)x;
        float4* xsv = (float4*)xs;
        #pragma unroll
        for (int i = threadIdx.x; i < GEMM_ROWS * 32; i += 256) {
            int r = row0 + (i >> 5);
            xsv[i] = (r < N_NODES) ? xg[(size_t)r * 32 + (i & 31)]
                                   : make_float4(0.f, 0.f, 0.f, 0.f);
        }
    }
    __syncthreads();

    int jq = threadIdx.x & 31;
    int rg = threadIdx.x >> 5;

    unsigned long long acc[8][2];
    #pragma unroll
    for (int r = 0; r < 8; r++) { acc[r][0] = 0ull; acc[r][1] = 0ull; }

    const ulonglong2* ws2 = (const ulonglong2*)ws;   // 32 ulonglong2 per k-row
    const float4* xs4 = (const float4*)xs;

    #pragma unroll 2
    for (int k4 = 0; k4 < D / 4; k4++) {
        ulonglong2 w0 = ws2[(k4 * 4 + 0) * 32 + jq];
        ulonglong2 w1 = ws2[(k4 * 4 + 1) * 32 + jq];
        ulonglong2 w2 = ws2[(k4 * 4 + 2) * 32 + jq];
        ulonglong2 w3 = ws2[(k4 * 4 + 3) * 32 + jq];
        #pragma unroll
        for (int r = 0; r < 8; r++) {
            float4 xv = xs4[((rg << 3) + r) * 32 + k4];   // warp-uniform (broadcast)
            unsigned long long p;
            p = pack2(xv.x); FMA2(acc[r][0], p, w0.x); FMA2(acc[r][1], p, w0.y);
            p = pack2(xv.y); FMA2(acc[r][0], p, w1.x); FMA2(acc[r][1], p, w1.y);
            p = pack2(xv.z); FMA2(acc[r][0], p, w2.x); FMA2(acc[r][1], p, w2.y);
            p = pack2(xv.w); FMA2(acc[r][0], p, w3.x); FMA2(acc[r][1], p, w3.y);
        }
    }

    ulonglong2* hv = (ulonglong2*)g_h;
    #pragma unroll
    for (int r = 0; r < 8; r++) {
        int row = row0 + (rg << 3) + r;
        if (row < N_NODES) {
            ulonglong2 t; t.x = acc[r][0]; t.y = acc[r][1];
            hv[(size_t)row * 32 + jq] = t;
        }
    }
}

// per-block scan of deg -> local-exclusive rowptr + block sums; also dis = rsqrt(deg+1)
__global__ void k_scan1() {
    __shared__ int s[SCAN_B];
    int tid = threadIdx.x;
    int gid = blockIdx.x * SCAN_B + tid;
    int v = (gid < N_NODES) ? g_deg[gid] : 0;
    if (gid < N_NODES) g_dis[gid] = rsqrtf((float)(v + 1));
    s[tid] = v;
    __syncthreads();
    #pragma unroll
    for (int off = 1; off < SCAN_B; off <<= 1) {
        int t = (tid >= off) ? s[tid - off] : 0;
        __syncthreads();
        s[tid] += t;
        __syncthreads();
    }
    if (gid < N_NODES) g_rowptr[gid] = s[tid] - v;
    if (tid == SCAN_B - 1) g_bsums[blockIdx.x] = s[tid];
}

// each block sums its predecessor block totals, offsets rows, and zeroes deg
// (so the next graph replay's count starts from a clean slate)
__global__ void k_scan3() {
    __shared__ int s_off;
    if (threadIdx.x == 0) s_off = 0;
    __syncthreads();
    for (int t = threadIdx.x; t < blockIdx.x; t += blockDim.x)
        atomicAdd(&s_off, g_bsums[t]);
    __syncthreads();
    int off = s_off;
    int gid = blockIdx.x * SCAN_B + threadIdx.x;
    if (gid < N_NODES) {
        int r = g_rowptr[gid] + off;
        g_rowptr[gid] = r;
        g_cursor[gid] = r;
        g_deg[gid] = 0;
    }
    if (blockIdx.x == 0 && threadIdx.x == 0) g_rowptr[N_NODES] = N_EDGES;
}

__global__ void k_scatter(const int* __restrict__ src, const int* __restrict__ dst) {
    int e = blockIdx.x * blockDim.x + threadIdx.x;
    if (e < N_EDGES) {
        int d = dst[e];
        int pos = atomicAdd(&g_cursor[d], 1);
        g_col[pos] = src[e];
    }
}

// one warp per node; col/dis prefetched across lanes + shfl broadcast
__global__ void __launch_bounds__(256) k_agg(const float* __restrict__ b,
                                             float* __restrict__ out) {
    int node = blockIdx.x * 8 + (threadIdx.x >> 5);
    int lane = threadIdx.x & 31;
    if (node >= N_NODES) return;

    const float4* h4 = (const float4*)g_h;
    float di = g_dis[node];
    float4 hv = h4[(size_t)node * 32 + lane];
    float4 acc;
    acc.x = di * hv.x; acc.y = di * hv.y; acc.z = di * hv.z; acc.w = di * hv.w;

    int beg = g_rowptr[node];
    int cnt = g_rowptr[node + 1] - beg;

    for (int base = 0; base < cnt; base += 32) {
        int myi = base + lane;
        int sc = 0; float ns = 0.f;
        if (myi < cnt) {
            sc = __ldg(&g_col[beg + myi]);
            ns = __ldg(&g_dis[sc]);
        }
        int m = min(32, cnt - base);
        for (int t = 0; t < m; t++) {
            int   s  = __shfl_sync(0xffffffffu, sc, t);
            float nn = __shfl_sync(0xffffffffu, ns, t);
            float4 v = __ldg(&h4[(size_t)s * 32 + lane]);
            acc.x = fmaf(nn, v.x, acc.x);
            acc.y = fmaf(nn, v.y, acc.y);
            acc.z = fmaf(nn, v.z, acc.z);
            acc.w = fmaf(nn, v.w, acc.w);
        }
    }

    float4 bv = __ldg(&((const float4*)b)[lane]);
    float4 o;
    o.x = fmaxf(fmaf(di, acc.x, bv.x), 0.f);
    o.y = fmaxf(fmaf(di, acc.y, bv.y), 0.f);
    o.z = fmaxf(fmaf(di, acc.z, bv.z), 0.f);
    o.w = fmaxf(fmaf(di, acc.w, bv.w), 0.f);
    ((float4*)out)[(size_t)node * 32 + lane] = o;
}

// ---------------- launch ----------------
extern "C" void kernel_launch(void* const* d_in, const int* in_sizes, int n_in,
                              void* d_out, int out_size) {
    const float* x   = (const float*)d_in[0];
    const int*   ei  = (const int*)d_in[1];
    const float* W   = (const float*)d_in[2];
    const float* b   = (const float*)d_in[3];
    float* out = (float*)d_out;

    const int* src = ei;
    const int* dst = ei + N_EDGES;

    const int SMEM = 96 * 1024;
    cudaFuncSetAttribute(k_gemm_count, cudaFuncAttributeMaxDynamicSharedMemorySize, SMEM);

    const int TPB = 256;
    k_gemm_count<<<GEMM_BLOCKS, 256, SMEM>>>(x, W, dst);
    k_scan1<<<N_SCAN_BLOCKS, SCAN_B>>>();
    k_scan3<<<N_SCAN_BLOCKS, SCAN_B>>>();
    k_scatter<<<(N_EDGES + TPB - 1) / TPB, TPB>>>(src, dst);
    k_agg<<<(N_NODES + 7) / 8, 256>>>(b, out);
}

// round 5
// speedup vs baseline: 1.4105x; 1.0170x over previous
#include <cuda_runtime.h>
#include <cuda_bf16.h>
#include <cuda_fp16.h>

#define N_NODES 100000
#define N_EDGES 1600000
#define D 128

#define GEMM_ROWS   64
#define GEMM_BLOCKS ((N_NODES + GEMM_ROWS - 1) / GEMM_ROWS)   // 1563

// ---------------- static device scratch ----------------
__device__ __half g_h[(size_t)N_NODES * D];  // x @ W, fp16
__device__ float g_dis[N_NODES];             // deg^{-1/2}
__device__ int   g_deg[N_NODES];             // zero at load; re-zeroed by k_scan3
__device__ int   g_rowptr[N_NODES + 1];
__device__ int   g_cursor[N_NODES];
__device__ int   g_col[N_EDGES];
#define SCAN_B 1024
#define N_SCAN_BLOCKS ((N_NODES + SCAN_B - 1) / SCAN_B)   // 98
__device__ int   g_bsums[N_SCAN_BLOCKS];

// ---------------- f32x2 packed-FMA helpers ----------------
__device__ __forceinline__ unsigned long long pack2(float a) {
    unsigned long long u;
    asm("mov.b64 %0, {%1, %1};" : "=l"(u) : "f"(a));
    return u;
}
__device__ __forceinline__ float2 unpack2(unsigned long long u) {
    float2 f;
    asm("mov.b64 {%0, %1}, %2;" : "=f"(f.x), "=f"(f.y) : "l"(u));
    return f;
}
#define FMA2(d, a, b) \
    asm("fma.rn.f32x2 %0, %1, %2, %0;" : "+l"(d) : "l"(a), "l"(b))

// half2 <-> u32 bitcasts (compile to nothing)
__device__ __forceinline__ unsigned h2_to_u32(__half2 h) {
    return *reinterpret_cast<unsigned*>(&h);
}
__device__ __forceinline__ __half2 u32_to_h2(unsigned u) {
    return *reinterpret_cast<__half2*>(&u);
}

// ---------------- kernels ----------------

// degree count: 4 edges per thread (MLP 4)
__global__ void __launch_bounds__(256) k_count(const int* __restrict__ dst) {
    int e0 = (blockIdx.x * 256 + threadIdx.x) * 4;
    if (e0 + 3 < N_EDGES) {
        int4 d4 = *(const int4*)(dst + e0);
        atomicAdd(&g_deg[d4.x], 1);
        atomicAdd(&g_deg[d4.y], 1);
        atomicAdd(&g_deg[d4.z], 1);
        atomicAdd(&g_deg[d4.w], 1);
    } else {
        for (int i = 0; i < 4; i++)
            if (e0 + i < N_EDGES) atomicAdd(&g_deg[dst[e0 + i]], 1);
    }
}

// GEMM: h = x @ W, output fp16. 256 threads, 64 rows/block, W+x in 96KB smem.
__global__ void __launch_bounds__(256) k_gemm(const float* __restrict__ x,
                                              const float* __restrict__ W) {
    extern __shared__ float sm[];
    float* ws = sm;                 // W: 64KB
    float* xs = sm + D * D;         // x: 32KB

    int row0 = blockIdx.x * GEMM_ROWS;
    {
        const float4* Wg = (const float4*)W;
        float4* wsv = (float4*)ws;
        #pragma unroll
        for (int i = threadIdx.x; i < (D * D) / 4; i += 256)
            wsv[i] = Wg[i];
    }
    {
        const float4* xg = (const float4*)x;
        float4* xsv = (float4*)xs;
        #pragma unroll
        for (int i = threadIdx.x; i < GEMM_ROWS * 32; i += 256) {
            int r = row0 + (i >> 5);
            xsv[i] = (r < N_NODES) ? xg[(size_t)r * 32 + (i & 31)]
                                   : make_float4(0.f, 0.f, 0.f, 0.f);
        }
    }
    __syncthreads();

    int jq = threadIdx.x & 31;
    int rg = threadIdx.x >> 5;

    unsigned long long acc[8][2];
    #pragma unroll
    for (int r = 0; r < 8; r++) { acc[r][0] = 0ull; acc[r][1] = 0ull; }

    const ulonglong2* ws2 = (const ulonglong2*)ws;
    const float4* xs4 = (const float4*)xs;

    #pragma unroll 2
    for (int k4 = 0; k4 < D / 4; k4++) {
        ulonglong2 w0 = ws2[(k4 * 4 + 0) * 32 + jq];
        ulonglong2 w1 = ws2[(k4 * 4 + 1) * 32 + jq];
        ulonglong2 w2 = ws2[(k4 * 4 + 2) * 32 + jq];
        ulonglong2 w3 = ws2[(k4 * 4 + 3) * 32 + jq];
        #pragma unroll
        for (int r = 0; r < 8; r++) {
            float4 xv = xs4[((rg << 3) + r) * 32 + k4];   // warp-uniform broadcast
            unsigned long long p;
            p = pack2(xv.x); FMA2(acc[r][0], p, w0.x); FMA2(acc[r][1], p, w0.y);
            p = pack2(xv.y); FMA2(acc[r][0], p, w1.x); FMA2(acc[r][1], p, w1.y);
            p = pack2(xv.z); FMA2(acc[r][0], p, w2.x); FMA2(acc[r][1], p, w2.y);
            p = pack2(xv.w); FMA2(acc[r][0], p, w3.x); FMA2(acc[r][1], p, w3.y);
        }
    }

    uint2* hv = (uint2*)g_h;   // 32 uint2 (= 128 halves) per row
    #pragma unroll
    for (int r = 0; r < 8; r++) {
        int row = row0 + (rg << 3) + r;
        if (row < N_NODES) {
            float2 lo = unpack2(acc[r][0]);
            float2 hi = unpack2(acc[r][1]);
            uint2 st;
            st.x = h2_to_u32(__floats2half2_rn(lo.x, lo.y));
            st.y = h2_to_u32(__floats2half2_rn(hi.x, hi.y));
            hv[(size_t)row * 32 + jq] = st;
        }
    }
}

// warp-shuffle block scan: rowptr (local-exclusive) + block sums + dis
__global__ void k_scan1() {
    __shared__ int wsum[32];
    int tid = threadIdx.x;
    int lane = tid & 31, wid = tid >> 5;
    int gid = blockIdx.x * SCAN_B + tid;
    int v = (gid < N_NODES) ? g_deg[gid] : 0;
    if (gid < N_NODES) g_dis[gid] = rsqrtf((float)(v + 1));

    int xv = v;
    #pragma unroll
    for (int off = 1; off < 32; off <<= 1) {
        int t = __shfl_up_sync(0xffffffffu, xv, off);
        if (lane >= off) xv += t;
    }
    if (lane == 31) wsum[wid] = xv;
    __syncthreads();
    if (wid == 0) {
        int s = wsum[lane];
        #pragma unroll
        for (int off = 1; off < 32; off <<= 1) {
            int t = __shfl_up_sync(0xffffffffu, s, off);
            if (lane >= off) s += t;
        }
        wsum[lane] = s;
    }
    __syncthreads();
    int incl = xv + (wid > 0 ? wsum[wid - 1] : 0);
    if (gid < N_NODES) g_rowptr[gid] = incl - v;
    if (tid == SCAN_B - 1) g_bsums[blockIdx.x] = incl;
}

// offset rows by prefix of block sums; zero deg for next replay
__global__ void k_scan3() {
    __shared__ int s_off;
    if (threadIdx.x == 0) s_off = 0;
    __syncthreads();
    for (int t = threadIdx.x; t < blockIdx.x; t += blockDim.x)
        atomicAdd(&s_off, g_bsums[t]);
    __syncthreads();
    int off = s_off;
    int gid = blockIdx.x * SCAN_B + threadIdx.x;
    if (gid < N_NODES) {
        int r = g_rowptr[gid] + off;
        g_rowptr[gid] = r;
        g_cursor[gid] = r;
        g_deg[gid] = 0;
    }
    if (blockIdx.x == 0 && threadIdx.x == 0) g_rowptr[N_NODES] = N_EDGES;
}

// scatter: 2 edges per thread (MLP 2 on the atomic chain)
__global__ void __launch_bounds__(256) k_scatter(const int* __restrict__ src,
                                                 const int* __restrict__ dst) {
    int e0 = (blockIdx.x * 256 + threadIdx.x) * 2;
    if (e0 + 1 < N_EDGES) {
        int2 d2 = *(const int2*)(dst + e0);
        int2 s2 = *(const int2*)(src + e0);
        int p0 = atomicAdd(&g_cursor[d2.x], 1);
        int p1 = atomicAdd(&g_cursor[d2.y], 1);
        g_col[p0] = s2.x;
        g_col[p1] = s2.y;
    } else if (e0 < N_EDGES) {
        int p = atomicAdd(&g_cursor[dst[e0]], 1);
        g_col[p] = src[e0];
    }
}

// one warp per node; fp16 h gathers (uint2 = 4 halves per lane), fp32 accum
__global__ void __launch_bounds__(256) k_agg(const float* __restrict__ b,
                                             float* __restrict__ out) {
    int node = blockIdx.x * 8 + (threadIdx.x >> 5);
    int lane = threadIdx.x & 31;
    if (node >= N_NODES) return;

    const uint2* h2 = (const uint2*)g_h;
    float di = g_dis[node];

    uint2 hv = h2[(size_t)node * 32 + lane];
    float2 f0 = __half22float2(u32_to_h2(hv.x));
    float2 f1 = __half22float2(u32_to_h2(hv.y));
    float4 acc;
    acc.x = di * f0.x; acc.y = di * f0.y; acc.z = di * f1.x; acc.w = di * f1.y;

    int beg = g_rowptr[node];
    int cnt = g_rowptr[node + 1] - beg;

    for (int base = 0; base < cnt; base += 32) {
        int myi = base + lane;
        int sc = 0; float ns = 0.f;
        if (myi < cnt) {
            sc = __ldg(&g_col[beg + myi]);
            ns = __ldg(&g_dis[sc]);
        }
        int m = min(32, cnt - base);
        for (int t = 0; t < m; t++) {
            int   s  = __shfl_sync(0xffffffffu, sc, t);
            float nn = __shfl_sync(0xffffffffu, ns, t);
            uint2 v = __ldg(&h2[(size_t)s * 32 + lane]);
            float2 g0 = __half22float2(u32_to_h2(v.x));
            float2 g1 = __half22float2(u32_to_h2(v.y));
            acc.x = fmaf(nn, g0.x, acc.x);
            acc.y = fmaf(nn, g0.y, acc.y);
            acc.z = fmaf(nn, g1.x, acc.z);
            acc.w = fmaf(nn, g1.y, acc.w);
        }
    }

    float4 bv = __ldg(&((const float4*)b)[lane]);
    float4 o;
    o.x = fmaxf(fmaf(di, acc.x, bv.x), 0.f);
    o.y = fmaxf(fmaf(di, acc.y, bv.y), 0.f);
    o.z = fmaxf(fmaf(di, acc.z, bv.z), 0.f);
    o.w = fmaxf(fmaf(di, acc.w, bv.w), 0.f);
    ((float4*)out)[(size_t)node * 32 + lane] = o;
}

// ---------------- launch ----------------
extern "C" void kernel_launch(void* const* d_in, const int* in_sizes, int n_in,
                              void* d_out, int out_size) {
    const float* x   = (const float*)d_in[0];
    const int*   ei  = (const int*)d_in[1];
    const float* W   = (const float*)d_in[2];
    const float* b   = (const float*)d_in[3];
    float* out = (float*)d_out;

    const int* src = ei;
    const int* dst = ei + N_EDGES;

    static cudaStream_t sB = nullptr;
    static cudaEvent_t evFork = nullptr, evB = nullptr;
    if (sB == nullptr) {
        cudaStreamCreateWithFlags(&sB, cudaStreamNonBlocking);
        cudaEventCreateWithFlags(&evFork, cudaEventDisableTiming);
        cudaEventCreateWithFlags(&evB, cudaEventDisableTiming);
    }

    const int SMEM = 96 * 1024;
    cudaFuncSetAttribute(k_gemm, cudaFuncAttributeMaxDynamicSharedMemorySize, SMEM);

    // fork: GEMM on side stream, CSR build on main stream, join before agg
    cudaEventRecord(evFork, 0);
    cudaStreamWaitEvent(sB, evFork, 0);
    k_gemm<<<GEMM_BLOCKS, 256, SMEM, sB>>>(x, W);
    cudaEventRecord(evB, sB);

    k_count<<<(N_EDGES + 1023) / 1024, 256>>>(dst);
    k_scan1<<<N_SCAN_BLOCKS, SCAN_B>>>();
    k_scan3<<<N_SCAN_BLOCKS, SCAN_B>>>();
    k_scatter<<<(N_EDGES / 2 + 255) / 256, 256>>>(src, dst);

    cudaStreamWaitEvent(0, evB, 0);
    k_agg<<<(N_NODES + 7) / 8, 256>>>(b, out);
}

// round 6
// speedup vs baseline: 1.4811x; 1.0501x over previous
#include <cuda_runtime.h>
#include <cuda_bf16.h>
#include <cuda_fp16.h>

#define N_NODES 100000
#define N_EDGES 1600000
#define D 128

#define GEMM_ROWS   64
#define GEMM_BLOCKS ((N_NODES + GEMM_ROWS - 1) / GEMM_ROWS)   // 1563

// ---------------- static device scratch ----------------
__device__ __half g_h[(size_t)N_NODES * D];  // x @ W, fp16
__device__ float g_dis[N_NODES];             // deg^{-1/2}
__device__ int   g_deg[N_NODES];             // zero at load; re-zeroed by k_scan3
__device__ int   g_rowptr[N_NODES + 1];
__device__ int   g_cursor[N_NODES];
__device__ int   g_col[N_EDGES];
#define SCAN_B 1024
#define N_SCAN_BLOCKS ((N_NODES + SCAN_B - 1) / SCAN_B)   // 98
__device__ int   g_bsums[N_SCAN_BLOCKS];

// ---------------- f32x2 packed-FMA helpers ----------------
__device__ __forceinline__ unsigned long long pack2(float a) {
    unsigned long long u;
    asm("mov.b64 %0, {%1, %1};" : "=l"(u) : "f"(a));
    return u;
}
__device__ __forceinline__ float2 unpack2(unsigned long long u) {
    float2 f;
    asm("mov.b64 {%0, %1}, %2;" : "=f"(f.x), "=f"(f.y) : "l"(u));
    return f;
}
#define FMA2(d, a, b) \
    asm("fma.rn.f32x2 %0, %1, %2, %0;" : "+l"(d) : "l"(a), "l"(b))

__device__ __forceinline__ unsigned h2_to_u32(__half2 h) {
    return *reinterpret_cast<unsigned*>(&h);
}
__device__ __forceinline__ __half2 u32_to_h2(unsigned u) {
    return *reinterpret_cast<__half2*>(&u);
}

// ---------------- GEMM + inline degree count ----------------
__global__ void __launch_bounds__(256) k_gemm_count(const float* __restrict__ x,
                                                    const float* __restrict__ W,
                                                    const int* __restrict__ dst) {
    extern __shared__ float sm[];
    float* ws = sm;                 // W: 64KB
    float* xs = sm + D * D;         // x: 32KB

    // fire-and-forget degree count: 4 edges/thread, drains under the FMA loop
    {
        int e0 = (blockIdx.x * 256 + threadIdx.x) * 4;
        if (e0 + 3 < N_EDGES) {
            int4 d4 = *(const int4*)(dst + e0);
            atomicAdd(&g_deg[d4.x], 1);
            atomicAdd(&g_deg[d4.y], 1);
            atomicAdd(&g_deg[d4.z], 1);
            atomicAdd(&g_deg[d4.w], 1);
        } else {
            for (int i = 0; i < 4; i++)
                if (e0 + i < N_EDGES) atomicAdd(&g_deg[dst[e0 + i]], 1);
        }
    }

    int row0 = blockIdx.x * GEMM_ROWS;
    {
        const float4* Wg = (const float4*)W;
        float4* wsv = (float4*)ws;
        #pragma unroll
        for (int i = threadIdx.x; i < (D * D) / 4; i += 256)
            wsv[i] = Wg[i];
    }
    {
        const float4* xg = (const float4*)x;
        float4* xsv = (float4*)xs;
        #pragma unroll
        for (int i = threadIdx.x; i < GEMM_ROWS * 32; i += 256) {
            int r = row0 + (i >> 5);
            xsv[i] = (r < N_NODES) ? xg[(size_t)r * 32 + (i & 31)]
                                   : make_float4(0.f, 0.f, 0.f, 0.f);
        }
    }
    __syncthreads();

    int jq = threadIdx.x & 31;
    int rg = threadIdx.x >> 5;

    unsigned long long acc[8][2];
    #pragma unroll
    for (int r = 0; r < 8; r++) { acc[r][0] = 0ull; acc[r][1] = 0ull; }

    const ulonglong2* ws2 = (const ulonglong2*)ws;
    const float4* xs4 = (const float4*)xs;

    #pragma unroll 2
    for (int k4 = 0; k4 < D / 4; k4++) {
        ulonglong2 w0 = ws2[(k4 * 4 + 0) * 32 + jq];
        ulonglong2 w1 = ws2[(k4 * 4 + 1) * 32 + jq];
        ulonglong2 w2 = ws2[(k4 * 4 + 2) * 32 + jq];
        ulonglong2 w3 = ws2[(k4 * 4 + 3) * 32 + jq];
        #pragma unroll
        for (int r = 0; r < 8; r++) {
            float4 xv = xs4[((rg << 3) + r) * 32 + k4];   // warp-uniform broadcast
            unsigned long long p;
            p = pack2(xv.x); FMA2(acc[r][0], p, w0.x); FMA2(acc[r][1], p, w0.y);
            p = pack2(xv.y); FMA2(acc[r][0], p, w1.x); FMA2(acc[r][1], p, w1.y);
            p = pack2(xv.z); FMA2(acc[r][0], p, w2.x); FMA2(acc[r][1], p, w2.y);
            p = pack2(xv.w); FMA2(acc[r][0], p, w3.x); FMA2(acc[r][1], p, w3.y);
        }
    }

    uint2* hv = (uint2*)g_h;   // 32 uint2 (= 128 halves) per row
    #pragma unroll
    for (int r = 0; r < 8; r++) {
        int row = row0 + (rg << 3) + r;
        if (row < N_NODES) {
            float2 lo = unpack2(acc[r][0]);
            float2 hi = unpack2(acc[r][1]);
            uint2 st;
            st.x = h2_to_u32(__floats2half2_rn(lo.x, lo.y));
            st.y = h2_to_u32(__floats2half2_rn(hi.x, hi.y));
            hv[(size_t)row * 32 + jq] = st;
        }
    }
}

// warp-shuffle block scan: rowptr (local-exclusive) + block sums + dis
__global__ void k_scan1() {
    __shared__ int wsum[32];
    int tid = threadIdx.x;
    int lane = tid & 31, wid = tid >> 5;
    int gid = blockIdx.x * SCAN_B + tid;
    int v = (gid < N_NODES) ? g_deg[gid] : 0;
    if (gid < N_NODES) g_dis[gid] = rsqrtf((float)(v + 1));

    int xv = v;
    #pragma unroll
    for (int off = 1; off < 32; off <<= 1) {
        int t = __shfl_up_sync(0xffffffffu, xv, off);
        if (lane >= off) xv += t;
    }
    if (lane == 31) wsum[wid] = xv;
    __syncthreads();
    if (wid == 0) {
        int s = wsum[lane];
        #pragma unroll
        for (int off = 1; off < 32; off <<= 1) {
            int t = __shfl_up_sync(0xffffffffu, s, off);
            if (lane >= off) s += t;
        }
        wsum[lane] = s;
    }
    __syncthreads();
    int incl = xv + (wid > 0 ? wsum[wid - 1] : 0);
    if (gid < N_NODES) g_rowptr[gid] = incl - v;
    if (tid == SCAN_B - 1) g_bsums[blockIdx.x] = incl;
}

// offset rows by prefix of block sums; zero deg for next replay
__global__ void k_scan3() {
    __shared__ int s_off;
    if (threadIdx.x == 0) s_off = 0;
    __syncthreads();
    for (int t = threadIdx.x; t < blockIdx.x; t += blockDim.x)
        atomicAdd(&s_off, g_bsums[t]);
    __syncthreads();
    int off = s_off;
    int gid = blockIdx.x * SCAN_B + threadIdx.x;
    if (gid < N_NODES) {
        int r = g_rowptr[gid] + off;
        g_rowptr[gid] = r;
        g_cursor[gid] = r;
        g_deg[gid] = 0;
    }
    if (blockIdx.x == 0 && threadIdx.x == 0) g_rowptr[N_NODES] = N_EDGES;
}

// scatter: 2 edges per thread (independent atomics, MLP 2)
__global__ void __launch_bounds__(256) k_scatter(const int* __restrict__ src,
                                                 const int* __restrict__ dst) {
    int e0 = (blockIdx.x * 256 + threadIdx.x) * 2;
    if (e0 + 1 < N_EDGES) {
        int2 d2 = *(const int2*)(dst + e0);
        int2 s2 = *(const int2*)(src + e0);
        int p0 = atomicAdd(&g_cursor[d2.x], 1);
        int p1 = atomicAdd(&g_cursor[d2.y], 1);
        g_col[p0] = s2.x;
        g_col[p1] = s2.y;
    } else if (e0 < N_EDGES) {
        int p = atomicAdd(&g_cursor[dst[e0]], 1);
        g_col[p] = src[e0];
    }
}

// one warp per node; fp16 h gathers, edge-unrolled x2 for gather MLP
__global__ void __launch_bounds__(256) k_agg(const float* __restrict__ b,
                                             float* __restrict__ out) {
    int node = blockIdx.x * 8 + (threadIdx.x >> 5);
    int lane = threadIdx.x & 31;
    if (node >= N_NODES) return;

    const uint2* h2 = (const uint2*)g_h;
    float di = g_dis[node];

    uint2 hv = h2[(size_t)node * 32 + lane];
    float2 f0 = __half22float2(u32_to_h2(hv.x));
    float2 f1 = __half22float2(u32_to_h2(hv.y));
    float4 acc;
    acc.x = di * f0.x; acc.y = di * f0.y; acc.z = di * f1.x; acc.w = di * f1.y;

    int beg = g_rowptr[node];
    int cnt = g_rowptr[node + 1] - beg;

    for (int base = 0; base < cnt; base += 32) {
        int myi = base + lane;
        int sc = 0; float ns = 0.f;
        if (myi < cnt) {
            sc = __ldg(&g_col[beg + myi]);
            ns = __ldg(&g_dis[sc]);
        }
        int m = min(32, cnt - base);
        int t = 0;
        for (; t + 1 < m; t += 2) {
            int   s0 = __shfl_sync(0xffffffffu, sc, t);
            float n0 = __shfl_sync(0xffffffffu, ns, t);
            int   s1 = __shfl_sync(0xffffffffu, sc, t + 1);
            float n1 = __shfl_sync(0xffffffffu, ns, t + 1);
            uint2 v0 = __ldg(&h2[(size_t)s0 * 32 + lane]);
            uint2 v1 = __ldg(&h2[(size_t)s1 * 32 + lane]);
            float2 a0 = __half22float2(u32_to_h2(v0.x));
            float2 a1 = __half22float2(u32_to_h2(v0.y));
            float2 b0 = __half22float2(u32_to_h2(v1.x));
            float2 b1 = __half22float2(u32_to_h2(v1.y));
            acc.x = fmaf(n0, a0.x, acc.x);
            acc.y = fmaf(n0, a0.y, acc.y);
            acc.z = fmaf(n0, a1.x, acc.z);
            acc.w = fmaf(n0, a1.y, acc.w);
            acc.x = fmaf(n1, b0.x, acc.x);
            acc.y = fmaf(n1, b0.y, acc.y);
            acc.z = fmaf(n1, b1.x, acc.z);
            acc.w = fmaf(n1, b1.y, acc.w);
        }
        if (t < m) {
            int   s0 = __shfl_sync(0xffffffffu, sc, t);
            float n0 = __shfl_sync(0xffffffffu, ns, t);
            uint2 v0 = __ldg(&h2[(size_t)s0 * 32 + lane]);
            float2 a0 = __half22float2(u32_to_h2(v0.x));
            float2 a1 = __half22float2(u32_to_h2(v0.y));
            acc.x = fmaf(n0, a0.x, acc.x);
            acc.y = fmaf(n0, a0.y, acc.y);
            acc.z = fmaf(n0, a1.x, acc.z);
            acc.w = fmaf(n0, a1.y, acc.w);
        }
    }

    float4 bv = __ldg(&((const float4*)b)[lane]);
    float4 o;
    o.x = fmaxf(fmaf(di, acc.x, bv.x), 0.f);
    o.y = fmaxf(fmaf(di, acc.y, bv.y), 0.f);
    o.z = fmaxf(fmaf(di, acc.z, bv.z), 0.f);
    o.w = fmaxf(fmaf(di, acc.w, bv.w), 0.f);
    ((float4*)out)[(size_t)node * 32 + lane] = o;
}

// ---------------- launch ----------------
extern "C" void kernel_launch(void* const* d_in, const int* in_sizes, int n_in,
                              void* d_out, int out_size) {
    const float* x   = (const float*)d_in[0];
    const int*   ei  = (const int*)d_in[1];
    const float* W   = (const float*)d_in[2];
    const float* b   = (const float*)d_in[3];
    float* out = (float*)d_out;

    const int* src = ei;
    const int* dst = ei + N_EDGES;

    const int SMEM = 96 * 1024;
    cudaFuncSetAttribute(k_gemm_count, cudaFuncAttributeMaxDynamicSharedMemorySize, SMEM);

    k_gemm_count<<<GEMM_BLOCKS, 256, SMEM>>>(x, W, dst);
    k_scan1<<<N_SCAN_BLOCKS, SCAN_B>>>();
    k_scan3<<<N_SCAN_BLOCKS, SCAN_B>>>();
    k_scatter<<<(N_EDGES / 2 + 255) / 256, 256>>>(src, dst);
    k_agg<<<(N_NODES + 7) / 8, 256>>>(b, out);
}

// round 7
// speedup vs baseline: 2.0604x; 1.3911x over previous
#include <cuda_runtime.h>
#include <cuda_bf16.h>
#include <cuda_fp16.h>
#include <mma.h>

using namespace nvcuda;

#define N_NODES 100000
#define N_EDGES 1600000
#define D 128

#define GB_ROWS 128
#define GB_BLOCKS ((N_NODES + GB_ROWS - 1) / GB_ROWS)   // 782
#define LDH 136   // fp16 smem leading dim (pad 8)
#define LDC 132   // f32 staging leading dim (pad 4)

// ---------------- static device scratch ----------------
__device__ __half g_h[(size_t)N_NODES * D];  // x @ W, fp16
__device__ float g_dis[N_NODES];             // deg^{-1/2}
__device__ int   g_deg[N_NODES];             // zero at load; re-zeroed by k_scan3
__device__ int   g_rowptr[N_NODES + 1];
__device__ int   g_cursor[N_NODES];
__device__ int   g_col[N_EDGES];
#define SCAN_B 1024
#define N_SCAN_BLOCKS ((N_NODES + SCAN_B - 1) / SCAN_B)   // 98
__device__ int   g_bsums[N_SCAN_BLOCKS];

__device__ __forceinline__ unsigned h2_to_u32(__half2 h) {
    return *reinterpret_cast<unsigned*>(&h);
}
__device__ __forceinline__ __half2 u32_to_h2(unsigned u) {
    return *reinterpret_cast<__half2*>(&u);
}

// ---------------- GEMM (wmma fp16->fp32) + inline degree count ----------------
// smem: xh (128 x LDH halves) | wh (128 x LDH halves); f32 staging reuses same space.
__global__ void __launch_bounds__(256) k_gemm_count(const float* __restrict__ x,
                                                    const float* __restrict__ W,
                                                    const int* __restrict__ dst) {
    extern __shared__ __align__(16) char smraw[];
    __half* xh = (__half*)smraw;
    __half* wh = xh + 128 * LDH;
    float*  stage = (float*)smraw;

    // fire-and-forget degree count: 8 edges/thread
    {
        int e0 = (blockIdx.x * 256 + threadIdx.x) * 8;
        if (e0 + 7 < N_EDGES) {
            int4 a = *(const int4*)(dst + e0);
            int4 c = *(const int4*)(dst + e0 + 4);
            atomicAdd(&g_deg[a.x], 1); atomicAdd(&g_deg[a.y], 1);
            atomicAdd(&g_deg[a.z], 1); atomicAdd(&g_deg[a.w], 1);
            atomicAdd(&g_deg[c.x], 1); atomicAdd(&g_deg[c.y], 1);
            atomicAdd(&g_deg[c.z], 1); atomicAdd(&g_deg[c.w], 1);
        } else {
            for (int i = 0; i < 8; i++)
                if (e0 + i < N_EDGES) atomicAdd(&g_deg[dst[e0 + i]], 1);
        }
    }

    int row0 = blockIdx.x * GB_ROWS;

    // W -> fp16 smem
    {
        const float4* Wg = (const float4*)W;
        #pragma unroll
        for (int i = threadIdx.x; i < 128 * 32; i += 256) {
            int r = i >> 5, c4 = i & 31;
            float4 v = Wg[r * 32 + c4];
            uint2 st;
            st.x = h2_to_u32(__floats2half2_rn(v.x, v.y));
            st.y = h2_to_u32(__floats2half2_rn(v.z, v.w));
            *(uint2*)&wh[r * LDH + c4 * 4] = st;
        }
    }
    // x rows -> fp16 smem (zero-pad past N)
    {
        const float4* xg = (const float4*)x;
        #pragma unroll
        for (int i = threadIdx.x; i < 128 * 32; i += 256) {
            int r = i >> 5, c4 = i & 31;
            int gr = row0 + r;
            float4 v = (gr < N_NODES) ? xg[(size_t)gr * 32 + c4]
                                      : make_float4(0.f, 0.f, 0.f, 0.f);
            uint2 st;
            st.x = h2_to_u32(__floats2half2_rn(v.x, v.y));
            st.y = h2_to_u32(__floats2half2_rn(v.z, v.w));
            *(uint2*)&xh[r * LDH + c4 * 4] = st;
        }
    }
    __syncthreads();

    int warp = threadIdx.x >> 5;

    wmma::fragment<wmma::accumulator, 16, 16, 16, float> acc[8];
    #pragma unroll
    for (int nt = 0; nt < 8; nt++) wmma::fill_fragment(acc[nt], 0.0f);

    #pragma unroll
    for (int kt = 0; kt < 8; kt++) {
        wmma::fragment<wmma::matrix_a, 16, 16, 16, __half, wmma::row_major> af;
        wmma::load_matrix_sync(af, xh + (warp * 16) * LDH + kt * 16, LDH);
        #pragma unroll
        for (int nt = 0; nt < 8; nt++) {
            wmma::fragment<wmma::matrix_b, 16, 16, 16, __half, wmma::row_major> bf;
            wmma::load_matrix_sync(bf, wh + (kt * 16) * LDH + nt * 16, LDH);
            wmma::mma_sync(acc[nt], af, bf, acc[nt]);
        }
    }

    __syncthreads();   // all smem reads done; reuse as f32 staging
    #pragma unroll
    for (int nt = 0; nt < 8; nt++)
        wmma::store_matrix_sync(stage + (warp * 16) * LDC + nt * 16, acc[nt],
                                LDC, wmma::mem_row_major);
    __syncthreads();

    // convert staging -> fp16 g_h
    uint2* hv = (uint2*)g_h;
    #pragma unroll
    for (int i = threadIdx.x; i < 128 * 32; i += 256) {
        int r = i >> 5, q = i & 31;
        int row = row0 + r;
        if (row < N_NODES) {
            float4 v = *(const float4*)&stage[r * LDC + q * 4];
            uint2 st;
            st.x = h2_to_u32(__floats2half2_rn(v.x, v.y));
            st.y = h2_to_u32(__floats2half2_rn(v.z, v.w));
            hv[(size_t)row * 32 + q] = st;
        }
    }
}

// warp-shuffle block scan: rowptr (local-exclusive) + block sums + dis
__global__ void k_scan1() {
    __shared__ int wsum[32];
    int tid = threadIdx.x;
    int lane = tid & 31, wid = tid >> 5;
    int gid = blockIdx.x * SCAN_B + tid;
    int v = (gid < N_NODES) ? g_deg[gid] : 0;
    if (gid < N_NODES) g_dis[gid] = rsqrtf((float)(v + 1));

    int xv = v;
    #pragma unroll
    for (int off = 1; off < 32; off <<= 1) {
        int t = __shfl_up_sync(0xffffffffu, xv, off);
        if (lane >= off) xv += t;
    }
    if (lane == 31) wsum[wid] = xv;
    __syncthreads();
    if (wid == 0) {
        int s = wsum[lane];
        #pragma unroll
        for (int off = 1; off < 32; off <<= 1) {
            int t = __shfl_up_sync(0xffffffffu, s, off);
            if (lane >= off) s += t;
        }
        wsum[lane] = s;
    }
    __syncthreads();
    int incl = xv + (wid > 0 ? wsum[wid - 1] : 0);
    if (gid < N_NODES) g_rowptr[gid] = incl - v;
    if (tid == SCAN_B - 1) g_bsums[blockIdx.x] = incl;
}

// offset rows by prefix of block sums; zero deg for next replay
__global__ void k_scan3() {
    __shared__ int s_off;
    if (threadIdx.x == 0) s_off = 0;
    __syncthreads();
    for (int t = threadIdx.x; t < blockIdx.x; t += blockDim.x)
        atomicAdd(&s_off, g_bsums[t]);
    __syncthreads();
    int off = s_off;
    int gid = blockIdx.x * SCAN_B + threadIdx.x;
    if (gid < N_NODES) {
        int r = g_rowptr[gid] + off;
        g_rowptr[gid] = r;
        g_cursor[gid] = r;
        g_deg[gid] = 0;
    }
    if (blockIdx.x == 0 && threadIdx.x == 0) g_rowptr[N_NODES] = N_EDGES;
}

// scatter: 8 edges per thread (8 independent atomic+store chains)
__global__ void __launch_bounds__(256) k_scatter(const int* __restrict__ src,
                                                 const int* __restrict__ dst) {
    int e0 = (blockIdx.x * 256 + threadIdx.x) * 8;
    if (e0 + 7 < N_EDGES) {
        int4 d0 = *(const int4*)(dst + e0);
        int4 d1 = *(const int4*)(dst + e0 + 4);
        int4 s0 = *(const int4*)(src + e0);
        int4 s1 = *(const int4*)(src + e0 + 4);
        int p0 = atomicAdd(&g_cursor[d0.x], 1);
        int p1 = atomicAdd(&g_cursor[d0.y], 1);
        int p2 = atomicAdd(&g_cursor[d0.z], 1);
        int p3 = atomicAdd(&g_cursor[d0.w], 1);
        int p4 = atomicAdd(&g_cursor[d1.x], 1);
        int p5 = atomicAdd(&g_cursor[d1.y], 1);
        int p6 = atomicAdd(&g_cursor[d1.z], 1);
        int p7 = atomicAdd(&g_cursor[d1.w], 1);
        g_col[p0] = s0.x; g_col[p1] = s0.y; g_col[p2] = s0.z; g_col[p3] = s0.w;
        g_col[p4] = s1.x; g_col[p5] = s1.y; g_col[p6] = s1.z; g_col[p7] = s1.w;
    } else {
        for (int i = 0; i < 8; i++) {
            int e = e0 + i;
            if (e < N_EDGES) {
                int p = atomicAdd(&g_cursor[dst[e]], 1);
                g_col[p] = src[e];
            }
        }
    }
}

// one warp per node; fp16 h gathers, edge-unrolled x2 for gather MLP
__global__ void __launch_bounds__(256) k_agg(const float* __restrict__ b,
                                             float* __restrict__ out) {
    int node = blockIdx.x * 8 + (threadIdx.x >> 5);
    int lane = threadIdx.x & 31;
    if (node >= N_NODES) return;

    const uint2* h2 = (const uint2*)g_h;
    float di = g_dis[node];

    uint2 hv = h2[(size_t)node * 32 + lane];
    float2 f0 = __half22float2(u32_to_h2(hv.x));
    float2 f1 = __half22float2(u32_to_h2(hv.y));
    float4 acc;
    acc.x = di * f0.x; acc.y = di * f0.y; acc.z = di * f1.x; acc.w = di * f1.y;

    int beg = g_rowptr[node];
    int cnt = g_rowptr[node + 1] - beg;

    for (int base = 0; base < cnt; base += 32) {
        int myi = base + lane;
        int sc = 0; float ns = 0.f;
        if (myi < cnt) {
            sc = __ldg(&g_col[beg + myi]);
            ns = __ldg(&g_dis[sc]);
        }
        int m = min(32, cnt - base);
        int t = 0;
        for (; t + 1 < m; t += 2) {
            int   s0 = __shfl_sync(0xffffffffu, sc, t);
            float n0 = __shfl_sync(0xffffffffu, ns, t);
            int   s1 = __shfl_sync(0xffffffffu, sc, t + 1);
            float n1 = __shfl_sync(0xffffffffu, ns, t + 1);
            uint2 v0 = __ldg(&h2[(size_t)s0 * 32 + lane]);
            uint2 v1 = __ldg(&h2[(size_t)s1 * 32 + lane]);
            float2 a0 = __half22float2(u32_to_h2(v0.x));
            float2 a1 = __half22float2(u32_to_h2(v0.y));
            float2 b0 = __half22float2(u32_to_h2(v1.x));
            float2 b1 = __half22float2(u32_to_h2(v1.y));
            acc.x = fmaf(n0, a0.x, acc.x);
            acc.y = fmaf(n0, a0.y, acc.y);
            acc.z = fmaf(n0, a1.x, acc.z);
            acc.w = fmaf(n0, a1.y, acc.w);
            acc.x = fmaf(n1, b0.x, acc.x);
            acc.y = fmaf(n1, b0.y, acc.y);
            acc.z = fmaf(n1, b1.x, acc.z);
            acc.w = fmaf(n1, b1.y, acc.w);
        }
        if (t < m) {
            int   s0 = __shfl_sync(0xffffffffu, sc, t);
            float n0 = __shfl_sync(0xffffffffu, ns, t);
            uint2 v0 = __ldg(&h2[(size_t)s0 * 32 + lane]);
            float2 a0 = __half22float2(u32_to_h2(v0.x));
            float2 a1 = __half22float2(u32_to_h2(v0.y));
            acc.x = fmaf(n0, a0.x, acc.x);
            acc.y = fmaf(n0, a0.y, acc.y);
            acc.z = fmaf(n0, a1.x, acc.z);
            acc.w = fmaf(n0, a1.y, acc.w);
        }
    }

    float4 bv = __ldg(&((const float4*)b)[lane]);
    float4 o;
    o.x = fmaxf(fmaf(di, acc.x, bv.x), 0.f);
    o.y = fmaxf(fmaf(di, acc.y, bv.y), 0.f);
    o.z = fmaxf(fmaf(di, acc.z, bv.z), 0.f);
    o.w = fmaxf(fmaf(di, acc.w, bv.w), 0.f);
    ((float4*)out)[(size_t)node * 32 + lane] = o;
}

// ---------------- launch ----------------
extern "C" void kernel_launch(void* const* d_in, const int* in_sizes, int n_in,
                              void* d_out, int out_size) {
    const float* x   = (const float*)d_in[0];
    const int*   ei  = (const int*)d_in[1];
    const float* W   = (const float*)d_in[2];
    const float* b   = (const float*)d_in[3];
    float* out = (float*)d_out;

    const int* src = ei;
    const int* dst = ei + N_EDGES;

    const int SMEM = 2 * 128 * LDH * 2;   // 69632 bytes
    cudaFuncSetAttribute(k_gemm_count, cudaFuncAttributeMaxDynamicSharedMemorySize, SMEM);

    k_gemm_count<<<GB_BLOCKS, 256, SMEM>>>(x, W, dst);
    k_scan1<<<N_SCAN_BLOCKS, SCAN_B>>>();
    k_scan3<<<N_SCAN_BLOCKS, SCAN_B>>>();
    k_scatter<<<(N_EDGES / 8 + 255) / 256, 256>>>(src, dst);
    k_agg<<<(N_NODES + 7) / 8, 256>>>(b, out);
}

// round 8
// speedup vs baseline: 2.1521x; 1.0445x over previous
#include <cuda_runtime.h>
#include <cuda_bf16.h>
#include <cuda_fp16.h>
#include <mma.h>

using namespace nvcuda;

#define N_NODES 100000
#define N_EDGES 1600000
#define D 128

#define GB_ROWS 128
#define GB_BLOCKS ((N_NODES + GB_ROWS - 1) / GB_ROWS)   // 782
#define LDH 136   // fp16 smem leading dim (pad 8)
#define LDC 132   // f32 staging leading dim (pad 4)

// ---------------- static device scratch ----------------
__device__ __half g_h[(size_t)N_NODES * D];  // x @ W, fp16
__device__ float g_dis[N_NODES];             // deg^{-1/2}
__device__ int   g_deg[N_NODES];             // zero at load; re-zeroed by scan
__device__ int   g_rowptr[N_NODES + 1];
__device__ int   g_cursor[N_NODES];
__device__ int   g_col[N_EDGES];
#define SCAN_B 1024
#define N_SCAN_BLOCKS ((N_NODES + SCAN_B - 1) / SCAN_B)   // 98
__device__ int   g_post[N_SCAN_BLOCKS];      // block-total posts (total+1); zeroed by k_count

__device__ __forceinline__ unsigned h2_to_u32(__half2 h) {
    return *reinterpret_cast<unsigned*>(&h);
}
__device__ __forceinline__ __half2 u32_to_h2(unsigned u) {
    return *reinterpret_cast<__half2*>(&u);
}

// ---------------- degree count (+ reset scan posts for this replay) ----------------
__global__ void __launch_bounds__(256) k_count(const int* __restrict__ dst) {
    int gtid = blockIdx.x * 256 + threadIdx.x;
    if (gtid < N_SCAN_BLOCKS) g_post[gtid] = 0;
    int e0 = gtid * 4;
    if (e0 + 3 < N_EDGES) {
        int4 d4 = *(const int4*)(dst + e0);
        atomicAdd(&g_deg[d4.x], 1);
        atomicAdd(&g_deg[d4.y], 1);
        atomicAdd(&g_deg[d4.z], 1);
        atomicAdd(&g_deg[d4.w], 1);
    } else {
        for (int i = 0; i < 4; i++)
            if (e0 + i < N_EDGES) atomicAdd(&g_deg[dst[e0 + i]], 1);
    }
}

// ---------------- fused single-kernel scan ----------------
// 98 co-resident blocks (<=148 SMs, all wave-1). Each block: shfl scan of its
// 1024 degs, post total+1, poll predecessors' posts, apply offset. Also writes
// dis, cursor, and re-zeroes deg for the next graph replay.
__global__ void __launch_bounds__(SCAN_B) k_scan() {
    __shared__ int wsum[32];
    __shared__ int s_off;
    int tid = threadIdx.x;
    int lane = tid & 31, wid = tid >> 5;
    int gid = blockIdx.x * SCAN_B + tid;
    int v = (gid < N_NODES) ? g_deg[gid] : 0;
    if (gid < N_NODES) {
        g_dis[gid] = rsqrtf((float)(v + 1));
        g_deg[gid] = 0;
    }
    if (tid == 0) s_off = 0;

    int xv = v;
    #pragma unroll
    for (int off = 1; off < 32; off <<= 1) {
        int t = __shfl_up_sync(0xffffffffu, xv, off);
        if (lane >= off) xv += t;
    }
    if (lane == 31) wsum[wid] = xv;
    __syncthreads();
    if (wid == 0) {
        int s = wsum[lane];
        #pragma unroll
        for (int off = 1; off < 32; off <<= 1) {
            int t = __shfl_up_sync(0xffffffffu, s, off);
            if (lane >= off) s += t;
        }
        wsum[lane] = s;
    }
    __syncthreads();
    int incl = xv + (wid > 0 ? wsum[wid - 1] : 0);
    int btotal = wsum[31];

    // post this block's total (+1 so 0 means "not posted")
    if (tid == 0) {
        __threadfence();
        atomicExch(&g_post[blockIdx.x], btotal + 1);
    }
    // poll predecessors
    if (tid < blockIdx.x) {
        volatile int* p = g_post + tid;
        int pv;
        while ((pv = *p) == 0) { }
        atomicAdd(&s_off, pv - 1);
    }
    __syncthreads();
    int off = s_off;

    if (gid < N_NODES) {
        int r = incl - v + off;
        g_rowptr[gid] = r;
        g_cursor[gid] = r;
    }
    if (blockIdx.x == 0 && tid == 0) g_rowptr[N_NODES] = N_EDGES;
}

// ---------------- GEMM (wmma fp16->fp32) + inline CSR scatter ----------------
// Runs after k_scan (cursor ready). Scatter atomics issue first and drain
// under the MMA work.
__global__ void __launch_bounds__(256) k_gemm_scatter(const float* __restrict__ x,
                                                      const float* __restrict__ W,
                                                      const int* __restrict__ src,
                                                      const int* __restrict__ dst) {
    extern __shared__ __align__(16) char smraw[];
    __half* xh = (__half*)smraw;
    __half* wh = xh + 128 * LDH;
    float*  stage = (float*)smraw;

    // fire-and-forget scatter: 8 edges/thread
    {
        int e0 = (blockIdx.x * 256 + threadIdx.x) * 8;
        if (e0 + 7 < N_EDGES) {
            int4 d0 = *(const int4*)(dst + e0);
            int4 d1 = *(const int4*)(dst + e0 + 4);
            int4 s0 = *(const int4*)(src + e0);
            int4 s1 = *(const int4*)(src + e0 + 4);
            int p0 = atomicAdd(&g_cursor[d0.x], 1);
            int p1 = atomicAdd(&g_cursor[d0.y], 1);
            int p2 = atomicAdd(&g_cursor[d0.z], 1);
            int p3 = atomicAdd(&g_cursor[d0.w], 1);
            int p4 = atomicAdd(&g_cursor[d1.x], 1);
            int p5 = atomicAdd(&g_cursor[d1.y], 1);
            int p6 = atomicAdd(&g_cursor[d1.z], 1);
            int p7 = atomicAdd(&g_cursor[d1.w], 1);
            g_col[p0] = s0.x; g_col[p1] = s0.y; g_col[p2] = s0.z; g_col[p3] = s0.w;
            g_col[p4] = s1.x; g_col[p5] = s1.y; g_col[p6] = s1.z; g_col[p7] = s1.w;
        } else {
            for (int i = 0; i < 8; i++) {
                int e = e0 + i;
                if (e < N_EDGES) {
                    int p = atomicAdd(&g_cursor[dst[e]], 1);
                    g_col[p] = src[e];
                }
            }
        }
    }

    int row0 = blockIdx.x * GB_ROWS;

    // W -> fp16 smem
    {
        const float4* Wg = (const float4*)W;
        #pragma unroll
        for (int i = threadIdx.x; i < 128 * 32; i += 256) {
            int r = i >> 5, c4 = i & 31;
            float4 v = Wg[r * 32 + c4];
            uint2 st;
            st.x = h2_to_u32(__floats2half2_rn(v.x, v.y));
            st.y = h2_to_u32(__floats2half2_rn(v.z, v.w));
            *(uint2*)&wh[r * LDH + c4 * 4] = st;
        }
    }
    // x rows -> fp16 smem (zero-pad past N)
    {
        const float4* xg = (const float4*)x;
        #pragma unroll
        for (int i = threadIdx.x; i < 128 * 32; i += 256) {
            int r = i >> 5, c4 = i & 31;
            int gr = row0 + r;
            float4 v = (gr < N_NODES) ? xg[(size_t)gr * 32 + c4]
                                      : make_float4(0.f, 0.f, 0.f, 0.f);
            uint2 st;
            st.x = h2_to_u32(__floats2half2_rn(v.x, v.y));
            st.y = h2_to_u32(__floats2half2_rn(v.z, v.w));
            *(uint2*)&xh[r * LDH + c4 * 4] = st;
        }
    }
    __syncthreads();

    int warp = threadIdx.x >> 5;

    wmma::fragment<wmma::accumulator, 16, 16, 16, float> acc[8];
    #pragma unroll
    for (int nt = 0; nt < 8; nt++) wmma::fill_fragment(acc[nt], 0.0f);

    #pragma unroll
    for (int kt = 0; kt < 8; kt++) {
        wmma::fragment<wmma::matrix_a, 16, 16, 16, __half, wmma::row_major> af;
        wmma::load_matrix_sync(af, xh + (warp * 16) * LDH + kt * 16, LDH);
        #pragma unroll
        for (int nt = 0; nt < 8; nt++) {
            wmma::fragment<wmma::matrix_b, 16, 16, 16, __half, wmma::row_major> bf;
            wmma::load_matrix_sync(bf, wh + (kt * 16) * LDH + nt * 16, LDH);
            wmma::mma_sync(acc[nt], af, bf, acc[nt]);
        }
    }

    __syncthreads();   // all smem reads done; reuse as f32 staging
    #pragma unroll
    for (int nt = 0; nt < 8; nt++)
        wmma::store_matrix_sync(stage + (warp * 16) * LDC + nt * 16, acc[nt],
                                LDC, wmma::mem_row_major);
    __syncthreads();

    // convert staging -> fp16 g_h
    uint2* hv = (uint2*)g_h;
    #pragma unroll
    for (int i = threadIdx.x; i < 128 * 32; i += 256) {
        int r = i >> 5, q = i & 31;
        int row = row0 + r;
        if (row < N_NODES) {
            float4 v = *(const float4*)&stage[r * LDC + q * 4];
            uint2 st;
            st.x = h2_to_u32(__floats2half2_rn(v.x, v.y));
            st.y = h2_to_u32(__floats2half2_rn(v.z, v.w));
            hv[(size_t)row * 32 + q] = st;
        }
    }
}

// one warp per node; fp16 h gathers, edge-unrolled x2 for gather MLP
__global__ void __launch_bounds__(256) k_agg(const float* __restrict__ b,
                                             float* __restrict__ out) {
    int node = blockIdx.x * 8 + (threadIdx.x >> 5);
    int lane = threadIdx.x & 31;
    if (node >= N_NODES) return;

    const uint2* h2 = (const uint2*)g_h;
    float di = g_dis[node];

    uint2 hv = h2[(size_t)node * 32 + lane];
    float2 f0 = __half22float2(u32_to_h2(hv.x));
    float2 f1 = __half22float2(u32_to_h2(hv.y));
    float4 acc;
    acc.x = di * f0.x; acc.y = di * f0.y; acc.z = di * f1.x; acc.w = di * f1.y;

    int beg = g_rowptr[node];
    int cnt = g_rowptr[node + 1] - beg;

    for (int base = 0; base < cnt; base += 32) {
        int myi = base + lane;
        int sc = 0; float ns = 0.f;
        if (myi < cnt) {
            sc = __ldg(&g_col[beg + myi]);
            ns = __ldg(&g_dis[sc]);
        }
        int m = min(32, cnt - base);
        int t = 0;
        for (; t + 1 < m; t += 2) {
            int   s0 = __shfl_sync(0xffffffffu, sc, t);
            float n0 = __shfl_sync(0xffffffffu, ns, t);
            int   s1 = __shfl_sync(0xffffffffu, sc, t + 1);
            float n1 = __shfl_sync(0xffffffffu, ns, t + 1);
            uint2 v0 = __ldg(&h2[(size_t)s0 * 32 + lane]);
            uint2 v1 = __ldg(&h2[(size_t)s1 * 32 + lane]);
            float2 a0 = __half22float2(u32_to_h2(v0.x));
            float2 a1 = __half22float2(u32_to_h2(v0.y));
            float2 b0 = __half22float2(u32_to_h2(v1.x));
            float2 b1 = __half22float2(u32_to_h2(v1.y));
            acc.x = fmaf(n0, a0.x, acc.x);
            acc.y = fmaf(n0, a0.y, acc.y);
            acc.z = fmaf(n0, a1.x, acc.z);
            acc.w = fmaf(n0, a1.y, acc.w);
            acc.x = fmaf(n1, b0.x, acc.x);
            acc.y = fmaf(n1, b0.y, acc.y);
            acc.z = fmaf(n1, b1.x, acc.z);
            acc.w = fmaf(n1, b1.y, acc.w);
        }
        if (t < m) {
            int   s0 = __shfl_sync(0xffffffffu, sc, t);
            float n0 = __shfl_sync(0xffffffffu, ns, t);
            uint2 v0 = __ldg(&h2[(size_t)s0 * 32 + lane]);
            float2 a0 = __half22float2(u32_to_h2(v0.x));
            float2 a1 = __half22float2(u32_to_h2(v0.y));
            acc.x = fmaf(n0, a0.x, acc.x);
            acc.y = fmaf(n0, a0.y, acc.y);
            acc.z = fmaf(n0, a1.x, acc.z);
            acc.w = fmaf(n0, a1.y, acc.w);
        }
    }

    float4 bv = __ldg(&((const float4*)b)[lane]);
    float4 o;
    o.x = fmaxf(fmaf(di, acc.x, bv.x), 0.f);
    o.y = fmaxf(fmaf(di, acc.y, bv.y), 0.f);
    o.z = fmaxf(fmaf(di, acc.z, bv.z), 0.f);
    o.w = fmaxf(fmaf(di, acc.w, bv.w), 0.f);
    ((float4*)out)[(size_t)node * 32 + lane] = o;
}

// ---------------- launch ----------------
extern "C" void kernel_launch(void* const* d_in, const int* in_sizes, int n_in,
                              void* d_out, int out_size) {
    const float* x   = (const float*)d_in[0];
    const int*   ei  = (const int*)d_in[1];
    const float* W   = (const float*)d_in[2];
    const float* b   = (const float*)d_in[3];
    float* out = (float*)d_out;

    const int* src = ei;
    const int* dst = ei + N_EDGES;

    const int SMEM = 2 * 128 * LDH * 2;   // 69632 bytes
    cudaFuncSetAttribute(k_gemm_scatter, cudaFuncAttributeMaxDynamicSharedMemorySize, SMEM);

    k_count<<<(N_EDGES / 4 + 255) / 256, 256>>>(dst);
    k_scan<<<N_SCAN_BLOCKS, SCAN_B>>>();
    k_gemm_scatter<<<GB_BLOCKS, 256, SMEM>>>(x, W, src, dst);
    k_agg<<<(N_NODES + 7) / 8, 256>>>(b, out);
}

// round 9
// speedup vs baseline: 2.2705x; 1.0550x over previous
#include <cuda_runtime.h>
#include <cuda_bf16.h>
#include <cuda_fp16.h>
#include <mma.h>

using namespace nvcuda;

#define N_NODES 100000
#define N_EDGES 1600000
#define D 128

#define GB_ROWS 128
#define GB_BLOCKS ((N_NODES + GB_ROWS - 1) / GB_ROWS)   // 782
#define LDH 136   // fp16 smem leading dim (pad 8)
#define LDC 132   // f32 staging leading dim (pad 4)

// ---------------- static device scratch ----------------
__device__ __half g_h[(size_t)N_NODES * D];  // hn = dis .* (x @ W), fp16
__device__ float g_dis[N_NODES];             // deg^{-1/2}
__device__ int   g_deg[N_NODES];             // zero at load; re-zeroed by scan
__device__ int   g_rowptr[N_NODES + 1];
__device__ int   g_cursor[N_NODES];
__device__ int   g_col[N_EDGES];
#define SCAN_B 1024
#define N_SCAN_BLOCKS ((N_NODES + SCAN_B - 1) / SCAN_B)   // 98
__device__ int   g_post[N_SCAN_BLOCKS];      // block-total posts (total+1); zeroed by k_count

__device__ __forceinline__ unsigned h2_to_u32(__half2 h) {
    return *reinterpret_cast<unsigned*>(&h);
}
__device__ __forceinline__ __half2 u32_to_h2(unsigned u) {
    return *reinterpret_cast<__half2*>(&u);
}

// ---------------- degree count (+ reset scan posts for this replay) ----------------
__global__ void __launch_bounds__(256) k_count(const int* __restrict__ dst) {
    int gtid = blockIdx.x * 256 + threadIdx.x;
    if (gtid < N_SCAN_BLOCKS) g_post[gtid] = 0;
    int e0 = gtid * 4;
    if (e0 + 3 < N_EDGES) {
        int4 d4 = *(const int4*)(dst + e0);
        atomicAdd(&g_deg[d4.x], 1);
        atomicAdd(&g_deg[d4.y], 1);
        atomicAdd(&g_deg[d4.z], 1);
        atomicAdd(&g_deg[d4.w], 1);
    } else {
        for (int i = 0; i < 4; i++)
            if (e0 + i < N_EDGES) atomicAdd(&g_deg[dst[e0 + i]], 1);
    }
}

// ---------------- fused single-kernel scan (98 co-resident blocks) ----------------
__global__ void __launch_bounds__(SCAN_B) k_scan() {
    __shared__ int wsum[32];
    __shared__ int s_off;
    int tid = threadIdx.x;
    int lane = tid & 31, wid = tid >> 5;
    int gid = blockIdx.x * SCAN_B + tid;
    int v = (gid < N_NODES) ? g_deg[gid] : 0;
    if (gid < N_NODES) {
        g_dis[gid] = rsqrtf((float)(v + 1));
        g_deg[gid] = 0;
    }
    if (tid == 0) s_off = 0;

    int xv = v;
    #pragma unroll
    for (int off = 1; off < 32; off <<= 1) {
        int t = __shfl_up_sync(0xffffffffu, xv, off);
        if (lane >= off) xv += t;
    }
    if (lane == 31) wsum[wid] = xv;
    __syncthreads();
    if (wid == 0) {
        int s = wsum[lane];
        #pragma unroll
        for (int off = 1; off < 32; off <<= 1) {
            int t = __shfl_up_sync(0xffffffffu, s, off);
            if (lane >= off) s += t;
        }
        wsum[lane] = s;
    }
    __syncthreads();
    int incl = xv + (wid > 0 ? wsum[wid - 1] : 0);
    int btotal = wsum[31];

    if (tid == 0) {
        __threadfence();
        atomicExch(&g_post[blockIdx.x], btotal + 1);
    }
    if (tid < blockIdx.x) {
        volatile int* p = g_post + tid;
        int pv;
        while ((pv = *p) == 0) { }
        atomicAdd(&s_off, pv - 1);
    }
    __syncthreads();
    int off = s_off;

    if (gid < N_NODES) {
        int r = incl - v + off;
        g_rowptr[gid] = r;
        g_cursor[gid] = r;
    }
    if (blockIdx.x == 0 && tid == 0) g_rowptr[N_NODES] = N_EDGES;
}

// ---------------- GEMM (wmma, x pre-scaled by dis) + inline CSR scatter ----------------
// Computes hn = (dis .* x) @ W in fp16. Scatter atomics drain under the MMA work.
__global__ void __launch_bounds__(256) k_gemm_scatter(const float* __restrict__ x,
                                                      const float* __restrict__ W,
                                                      const int* __restrict__ src,
                                                      const int* __restrict__ dst) {
    extern __shared__ __align__(16) char smraw[];
    __half* xh = (__half*)smraw;
    __half* wh = xh + 128 * LDH;
    float*  stage = (float*)smraw;

    // fire-and-forget scatter: 8 edges/thread
    {
        int e0 = (blockIdx.x * 256 + threadIdx.x) * 8;
        if (e0 + 7 < N_EDGES) {
            int4 d0 = *(const int4*)(dst + e0);
            int4 d1 = *(const int4*)(dst + e0 + 4);
            int4 s0 = *(const int4*)(src + e0);
            int4 s1 = *(const int4*)(src + e0 + 4);
            int p0 = atomicAdd(&g_cursor[d0.x], 1);
            int p1 = atomicAdd(&g_cursor[d0.y], 1);
            int p2 = atomicAdd(&g_cursor[d0.z], 1);
            int p3 = atomicAdd(&g_cursor[d0.w], 1);
            int p4 = atomicAdd(&g_cursor[d1.x], 1);
            int p5 = atomicAdd(&g_cursor[d1.y], 1);
            int p6 = atomicAdd(&g_cursor[d1.z], 1);
            int p7 = atomicAdd(&g_cursor[d1.w], 1);
            g_col[p0] = s0.x; g_col[p1] = s0.y; g_col[p2] = s0.z; g_col[p3] = s0.w;
            g_col[p4] = s1.x; g_col[p5] = s1.y; g_col[p6] = s1.z; g_col[p7] = s1.w;
        } else {
            for (int i = 0; i < 8; i++) {
                int e = e0 + i;
                if (e < N_EDGES) {
                    int p = atomicAdd(&g_cursor[dst[e]], 1);
                    g_col[p] = src[e];
                }
            }
        }
    }

    int row0 = blockIdx.x * GB_ROWS;

    // W -> fp16 smem
    {
        const float4* Wg = (const float4*)W;
        #pragma unroll
        for (int i = threadIdx.x; i < 128 * 32; i += 256) {
            int r = i >> 5, c4 = i & 31;
            float4 v = Wg[r * 32 + c4];
            uint2 st;
            st.x = h2_to_u32(__floats2half2_rn(v.x, v.y));
            st.y = h2_to_u32(__floats2half2_rn(v.z, v.w));
            *(uint2*)&wh[r * LDH + c4 * 4] = st;
        }
    }
    // x rows scaled by dis -> fp16 smem (zero-pad past N)
    {
        const float4* xg = (const float4*)x;
        #pragma unroll
        for (int i = threadIdx.x; i < 128 * 32; i += 256) {
            int r = i >> 5, c4 = i & 31;
            int gr = row0 + r;
            float dv = 0.f;
            float4 v = make_float4(0.f, 0.f, 0.f, 0.f);
            if (gr < N_NODES) {
                dv = __ldg(&g_dis[gr]);           // broadcast within each 32-thread group
                v = xg[(size_t)gr * 32 + c4];
            }
            uint2 st;
            st.x = h2_to_u32(__floats2half2_rn(v.x * dv, v.y * dv));
            st.y = h2_to_u32(__floats2half2_rn(v.z * dv, v.w * dv));
            *(uint2*)&xh[r * LDH + c4 * 4] = st;
        }
    }
    __syncthreads();

    int warp = threadIdx.x >> 5;

    wmma::fragment<wmma::accumulator, 16, 16, 16, float> acc[8];
    #pragma unroll
    for (int nt = 0; nt < 8; nt++) wmma::fill_fragment(acc[nt], 0.0f);

    #pragma unroll
    for (int kt = 0; kt < 8; kt++) {
        wmma::fragment<wmma::matrix_a, 16, 16, 16, __half, wmma::row_major> af;
        wmma::load_matrix_sync(af, xh + (warp * 16) * LDH + kt * 16, LDH);
        #pragma unroll
        for (int nt = 0; nt < 8; nt++) {
            wmma::fragment<wmma::matrix_b, 16, 16, 16, __half, wmma::row_major> bf;
            wmma::load_matrix_sync(bf, wh + (kt * 16) * LDH + nt * 16, LDH);
            wmma::mma_sync(acc[nt], af, bf, acc[nt]);
        }
    }

    __syncthreads();
    #pragma unroll
    for (int nt = 0; nt < 8; nt++)
        wmma::store_matrix_sync(stage + (warp * 16) * LDC + nt * 16, acc[nt],
                                LDC, wmma::mem_row_major);
    __syncthreads();

    uint2* hv = (uint2*)g_h;
    #pragma unroll
    for (int i = threadIdx.x; i < 128 * 32; i += 256) {
        int r = i >> 5, q = i & 31;
        int row = row0 + r;
        if (row < N_NODES) {
            float4 v = *(const float4*)&stage[r * LDC + q * 4];
            uint2 st;
            st.x = h2_to_u32(__floats2half2_rn(v.x, v.y));
            st.y = h2_to_u32(__floats2half2_rn(v.z, v.w));
            hv[(size_t)row * 32 + q] = st;
        }
    }
}

// one warp per node: acc = hn[i] + sum_s hn[s]; out = relu(di*acc + b).
// No per-edge norm: just broadcast col + gather + add. Unroll x4.
__global__ void __launch_bounds__(256) k_agg(const float* __restrict__ b,
                                             float* __restrict__ out) {
    int node = blockIdx.x * 8 + (threadIdx.x >> 5);
    int lane = threadIdx.x & 31;
    if (node >= N_NODES) return;

    const uint2* h2 = (const uint2*)g_h;
    float di = g_dis[node];

    uint2 hv = h2[(size_t)node * 32 + lane];
    float2 f0 = __half22float2(u32_to_h2(hv.x));
    float2 f1 = __half22float2(u32_to_h2(hv.y));
    float4 acc;
    acc.x = f0.x; acc.y = f0.y; acc.z = f1.x; acc.w = f1.y;   // self term = hn[i]

    int beg = g_rowptr[node];
    int cnt = g_rowptr[node + 1] - beg;

    for (int base = 0; base < cnt; base += 32) {
        int myi = base + lane;
        int sc = (myi < cnt) ? __ldg(&g_col[beg + myi]) : 0;
        int m = min(32, cnt - base);
        int t = 0;
        for (; t + 3 < m; t += 4) {
            int s0 = __shfl_sync(0xffffffffu, sc, t);
            int s1 = __shfl_sync(0xffffffffu, sc, t + 1);
            int s2 = __shfl_sync(0xffffffffu, sc, t + 2);
            int s3 = __shfl_sync(0xffffffffu, sc, t + 3);
            uint2 v0 = __ldg(&h2[(size_t)s0 * 32 + lane]);
            uint2 v1 = __ldg(&h2[(size_t)s1 * 32 + lane]);
            uint2 v2 = __ldg(&h2[(size_t)s2 * 32 + lane]);
            uint2 v3 = __ldg(&h2[(size_t)s3 * 32 + lane]);
            float2 a0 = __half22float2(u32_to_h2(v0.x));
            float2 a1 = __half22float2(u32_to_h2(v0.y));
            float2 b0 = __half22float2(u32_to_h2(v1.x));
            float2 b1 = __half22float2(u32_to_h2(v1.y));
            float2 c0 = __half22float2(u32_to_h2(v2.x));
            float2 c1 = __half22float2(u32_to_h2(v2.y));
            float2 d0 = __half22float2(u32_to_h2(v3.x));
            float2 d1 = __half22float2(u32_to_h2(v3.y));
            acc.x += a0.x + b0.x;
            acc.y += a0.y + b0.y;
            acc.z += a1.x + b1.x;
            acc.w += a1.y + b1.y;
            acc.x += c0.x + d0.x;
            acc.y += c0.y + d0.y;
            acc.z += c1.x + d1.x;
            acc.w += c1.y + d1.y;
        }
        for (; t < m; t++) {
            int s0 = __shfl_sync(0xffffffffu, sc, t);
            uint2 v0 = __ldg(&h2[(size_t)s0 * 32 + lane]);
            float2 a0 = __half22float2(u32_to_h2(v0.x));
            float2 a1 = __half22float2(u32_to_h2(v0.y));
            acc.x += a0.x;
            acc.y += a0.y;
            acc.z += a1.x;
            acc.w += a1.y;
        }
    }

    float4 bv = __ldg(&((const float4*)b)[lane]);
    float4 o;
    o.x = fmaxf(fmaf(di, acc.x, bv.x), 0.f);
    o.y = fmaxf(fmaf(di, acc.y, bv.y), 0.f);
    o.z = fmaxf(fmaf(di, acc.z, bv.z), 0.f);
    o.w = fmaxf(fmaf(di, acc.w, bv.w), 0.f);
    ((float4*)out)[(size_t)node * 32 + lane] = o;
}

// ---------------- launch ----------------
extern "C" void kernel_launch(void* const* d_in, const int* in_sizes, int n_in,
                              void* d_out, int out_size) {
    const float* x   = (const float*)d_in[0];
    const int*   ei  = (const int*)d_in[1];
    const float* W   = (const float*)d_in[2];
    const float* b   = (const float*)d_in[3];
    float* out = (float*)d_out;

    const int* src = ei;
    const int* dst = ei + N_EDGES;

    const int SMEM = 2 * 128 * LDH * 2;   // 69632 bytes
    cudaFuncSetAttribute(k_gemm_scatter, cudaFuncAttributeMaxDynamicSharedMemorySize, SMEM);

    k_count<<<(N_EDGES / 4 + 255) / 256, 256>>>(dst);
    k_scan<<<N_SCAN_BLOCKS, SCAN_B>>>();
    k_gemm_scatter<<<GB_BLOCKS, 256, SMEM>>>(x, W, src, dst);
    k_agg<<<(N_NODES + 7) / 8, 256>>>(b, out);
}

// round 10
// speedup vs baseline: 2.3479x; 1.0341x over previous
#include <cuda_runtime.h>
#include <cuda_bf16.h>
#include <cuda_fp16.h>
#include <mma.h>

using namespace nvcuda;

#define N_NODES 100000
#define N_EDGES 1600000
#define D 128

#define GB_ROWS 128
#define GB_BLOCKS ((N_NODES + GB_ROWS - 1) / GB_ROWS)   // 782
#define LDH 136   // fp16 smem leading dim (pad 8)
#define LDC 132   // f32 staging leading dim (pad 4)

// ---------------- static device scratch ----------------
__device__ __half g_h[(size_t)N_NODES * D];  // hn = dis .* (x @ W), fp16
__device__ float g_dis[N_NODES];             // deg^{-1/2}
__device__ int   g_deg[N_NODES];             // zero at load; re-zeroed by scan
__device__ int   g_rowptr[N_NODES + 1];
__device__ int   g_cursor[N_NODES];
__device__ int   g_col[N_EDGES];
#define SCAN_B 1024
#define N_SCAN_BLOCKS ((N_NODES + SCAN_B - 1) / SCAN_B)   // 98
__device__ int   g_post[N_SCAN_BLOCKS];      // block-total posts (total+1); zeroed by k_count

__device__ __forceinline__ unsigned h2_to_u32(__half2 h) {
    return *reinterpret_cast<unsigned*>(&h);
}
__device__ __forceinline__ __half2 u32_to_h2(unsigned u) {
    return *reinterpret_cast<__half2*>(&u);
}

// ---------------- degree count (+ reset scan posts for this replay) ----------------
__global__ void __launch_bounds__(256) k_count(const int* __restrict__ dst) {
    int gtid = blockIdx.x * 256 + threadIdx.x;
    if (gtid < N_SCAN_BLOCKS) g_post[gtid] = 0;
    int e0 = gtid * 4;
    if (e0 + 3 < N_EDGES) {
        int4 d4 = *(const int4*)(dst + e0);
        atomicAdd(&g_deg[d4.x], 1);
        atomicAdd(&g_deg[d4.y], 1);
        atomicAdd(&g_deg[d4.z], 1);
        atomicAdd(&g_deg[d4.w], 1);
    } else {
        for (int i = 0; i < 4; i++)
            if (e0 + i < N_EDGES) atomicAdd(&g_deg[dst[e0 + i]], 1);
    }
}

// ---------------- fused single-kernel scan (98 co-resident blocks) ----------------
__global__ void __launch_bounds__(SCAN_B) k_scan() {
    __shared__ int wsum[32];
    __shared__ int s_off;
    int tid = threadIdx.x;
    int lane = tid & 31, wid = tid >> 5;
    int gid = blockIdx.x * SCAN_B + tid;
    int v = (gid < N_NODES) ? g_deg[gid] : 0;
    if (gid < N_NODES) {
        g_dis[gid] = rsqrtf((float)(v + 1));
        g_deg[gid] = 0;
    }
    if (tid == 0) s_off = 0;

    int xv = v;
    #pragma unroll
    for (int off = 1; off < 32; off <<= 1) {
        int t = __shfl_up_sync(0xffffffffu, xv, off);
        if (lane >= off) xv += t;
    }
    if (lane == 31) wsum[wid] = xv;
    __syncthreads();
    if (wid == 0) {
        int s = wsum[lane];
        #pragma unroll
        for (int off = 1; off < 32; off <<= 1) {
            int t = __shfl_up_sync(0xffffffffu, s, off);
            if (lane >= off) s += t;
        }
        wsum[lane] = s;
    }
    __syncthreads();
    int incl = xv + (wid > 0 ? wsum[wid - 1] : 0);
    int btotal = wsum[31];

    if (tid == 0) {
        __threadfence();
        atomicExch(&g_post[blockIdx.x], btotal + 1);
    }
    if (tid < blockIdx.x) {
        volatile int* p = g_post + tid;
        int pv;
        while ((pv = *p) == 0) { }
        atomicAdd(&s_off, pv - 1);
    }
    __syncthreads();
    int off = s_off;

    if (gid < N_NODES) {
        int r = incl - v + off;
        g_rowptr[gid] = r;
        g_cursor[gid] = r;
    }
    if (blockIdx.x == 0 && tid == 0) g_rowptr[N_NODES] = N_EDGES;
}

// ---------------- GEMM (wmma, x pre-scaled by dis) + inline CSR scatter ----------------
__global__ void __launch_bounds__(256) k_gemm_scatter(const float* __restrict__ x,
                                                      const float* __restrict__ W,
                                                      const int* __restrict__ src,
                                                      const int* __restrict__ dst) {
    extern __shared__ __align__(16) char smraw[];
    __half* xh = (__half*)smraw;
    __half* wh = xh + 128 * LDH;
    float*  stage = (float*)smraw;

    // fire-and-forget scatter: 8 edges/thread, drains under the MMA work
    {
        int e0 = (blockIdx.x * 256 + threadIdx.x) * 8;
        if (e0 + 7 < N_EDGES) {
            int4 d0 = *(const int4*)(dst + e0);
            int4 d1 = *(const int4*)(dst + e0 + 4);
            int4 s0 = *(const int4*)(src + e0);
            int4 s1 = *(const int4*)(src + e0 + 4);
            int p0 = atomicAdd(&g_cursor[d0.x], 1);
            int p1 = atomicAdd(&g_cursor[d0.y], 1);
            int p2 = atomicAdd(&g_cursor[d0.z], 1);
            int p3 = atomicAdd(&g_cursor[d0.w], 1);
            int p4 = atomicAdd(&g_cursor[d1.x], 1);
            int p5 = atomicAdd(&g_cursor[d1.y], 1);
            int p6 = atomicAdd(&g_cursor[d1.z], 1);
            int p7 = atomicAdd(&g_cursor[d1.w], 1);
            g_col[p0] = s0.x; g_col[p1] = s0.y; g_col[p2] = s0.z; g_col[p3] = s0.w;
            g_col[p4] = s1.x; g_col[p5] = s1.y; g_col[p6] = s1.z; g_col[p7] = s1.w;
        } else {
            for (int i = 0; i < 8; i++) {
                int e = e0 + i;
                if (e < N_EDGES) {
                    int p = atomicAdd(&g_cursor[dst[e]], 1);
                    g_col[p] = src[e];
                }
            }
        }
    }

    int row0 = blockIdx.x * GB_ROWS;

    // W -> fp16 smem
    {
        const float4* Wg = (const float4*)W;
        #pragma unroll
        for (int i = threadIdx.x; i < 128 * 32; i += 256) {
            int r = i >> 5, c4 = i & 31;
            float4 v = Wg[r * 32 + c4];
            uint2 st;
            st.x = h2_to_u32(__floats2half2_rn(v.x, v.y));
            st.y = h2_to_u32(__floats2half2_rn(v.z, v.w));
            *(uint2*)&wh[r * LDH + c4 * 4] = st;
        }
    }
    // x rows scaled by dis -> fp16 smem (zero-pad past N)
    {
        const float4* xg = (const float4*)x;
        #pragma unroll
        for (int i = threadIdx.x; i < 128 * 32; i += 256) {
            int r = i >> 5, c4 = i & 31;
            int gr = row0 + r;
            float dv = 0.f;
            float4 v = make_float4(0.f, 0.f, 0.f, 0.f);
            if (gr < N_NODES) {
                dv = __ldg(&g_dis[gr]);
                v = xg[(size_t)gr * 32 + c4];
            }
            uint2 st;
            st.x = h2_to_u32(__floats2half2_rn(v.x * dv, v.y * dv));
            st.y = h2_to_u32(__floats2half2_rn(v.z * dv, v.w * dv));
            *(uint2*)&xh[r * LDH + c4 * 4] = st;
        }
    }
    __syncthreads();

    int warp = threadIdx.x >> 5;

    wmma::fragment<wmma::accumulator, 16, 16, 16, float> acc[8];
    #pragma unroll
    for (int nt = 0; nt < 8; nt++) wmma::fill_fragment(acc[nt], 0.0f);

    #pragma unroll
    for (int kt = 0; kt < 8; kt++) {
        wmma::fragment<wmma::matrix_a, 16, 16, 16, __half, wmma::row_major> af;
        wmma::load_matrix_sync(af, xh + (warp * 16) * LDH + kt * 16, LDH);
        #pragma unroll
        for (int nt = 0; nt < 8; nt++) {
            wmma::fragment<wmma::matrix_b, 16, 16, 16, __half, wmma::row_major> bf;
            wmma::load_matrix_sync(bf, wh + (kt * 16) * LDH + nt * 16, LDH);
            wmma::mma_sync(acc[nt], af, bf, acc[nt]);
        }
    }

    __syncthreads();
    #pragma unroll
    for (int nt = 0; nt < 8; nt++)
        wmma::store_matrix_sync(stage + (warp * 16) * LDC + nt * 16, acc[nt],
                                LDC, wmma::mem_row_major);
    __syncthreads();

    uint2* hv = (uint2*)g_h;
    #pragma unroll
    for (int i = threadIdx.x; i < 128 * 32; i += 256) {
        int r = i >> 5, q = i & 31;
        int row = row0 + r;
        if (row < N_NODES) {
            float4 v = *(const float4*)&stage[r * LDC + q * 4];
            uint2 st;
            st.x = h2_to_u32(__floats2half2_rn(v.x, v.y));
            st.y = h2_to_u32(__floats2half2_rn(v.z, v.w));
            hv[(size_t)row * 32 + q] = st;
        }
    }
}

// one warp per node: acc = hn[i] + sum_s hn[s]; out = relu(di*acc + b).
// 4 edges/step combined via 2-level HADD2 tree, one fp32 add per quad.
__global__ void __launch_bounds__(256) k_agg(const float* __restrict__ b,
                                             float* __restrict__ out) {
    int node = blockIdx.x * 8 + (threadIdx.x >> 5);
    int lane = threadIdx.x & 31;
    if (node >= N_NODES) return;

    const uint2* h2 = (const uint2*)g_h;
    float di = g_dis[node];

    uint2 hv = h2[(size_t)node * 32 + lane];
    float2 f0 = __half22float2(u32_to_h2(hv.x));
    float2 f1 = __half22float2(u32_to_h2(hv.y));
    float4 acc;
    acc.x = f0.x; acc.y = f0.y; acc.z = f1.x; acc.w = f1.y;   // self term = hn[i]

    int beg = g_rowptr[node];
    int cnt = g_rowptr[node + 1] - beg;

    for (int base = 0; base < cnt; base += 32) {
        int myi = base + lane;
        int sc = (myi < cnt) ? __ldg(&g_col[beg + myi]) : 0;
        int m = min(32, cnt - base);
        int t = 0;
        for (; t + 3 < m; t += 4) {
            int s0 = __shfl_sync(0xffffffffu, sc, t);
            int s1 = __shfl_sync(0xffffffffu, sc, t + 1);
            int s2 = __shfl_sync(0xffffffffu, sc, t + 2);
            int s3 = __shfl_sync(0xffffffffu, sc, t + 3);
            uint2 v0 = __ldg(&h2[(size_t)s0 * 32 + lane]);
            uint2 v1 = __ldg(&h2[(size_t)s1 * 32 + lane]);
            uint2 v2 = __ldg(&h2[(size_t)s2 * 32 + lane]);
            uint2 v3 = __ldg(&h2[(size_t)s3 * 32 + lane]);
            // 2-level fp16 tree: (v0+v1) + (v2+v3)
            __half2 p0 = __hadd2(u32_to_h2(v0.x), u32_to_h2(v1.x));
            __half2 p1 = __hadd2(u32_to_h2(v0.y), u32_to_h2(v1.y));
            __half2 q0 = __hadd2(u32_to_h2(v2.x), u32_to_h2(v3.x));
            __half2 q1 = __hadd2(u32_to_h2(v2.y), u32_to_h2(v3.y));
            __half2 r0 = __hadd2(p0, q0);
            __half2 r1 = __hadd2(p1, q1);
            float2 g0 = __half22float2(r0);
            float2 g1 = __half22float2(r1);
            acc.x += g0.x;
            acc.y += g0.y;
            acc.z += g1.x;
            acc.w += g1.y;
        }
        for (; t < m; t++) {
            int s0 = __shfl_sync(0xffffffffu, sc, t);
            uint2 v0 = __ldg(&h2[(size_t)s0 * 32 + lane]);
            float2 a0 = __half22float2(u32_to_h2(v0.x));
            float2 a1 = __half22float2(u32_to_h2(v0.y));
            acc.x += a0.x;
            acc.y += a0.y;
            acc.z += a1.x;
            acc.w += a1.y;
        }
    }

    float4 bv = __ldg(&((const float4*)b)[lane]);
    float4 o;
    o.x = fmaxf(fmaf(di, acc.x, bv.x), 0.f);
    o.y = fmaxf(fmaf(di, acc.y, bv.y), 0.f);
    o.z = fmaxf(fmaf(di, acc.z, bv.z), 0.f);
    o.w = fmaxf(fmaf(di, acc.w, bv.w), 0.f);
    ((float4*)out)[(size_t)node * 32 + lane] = o;
}

// ---------------- launch ----------------
extern "C" void kernel_launch(void* const* d_in, const int* in_sizes, int n_in,
                              void* d_out, int out_size) {
    const float* x   = (const float*)d_in[0];
    const int*   ei  = (const int*)d_in[1];
    const float* W   = (const float*)d_in[2];
    const float* b   = (const float*)d_in[3];
    float* out = (float*)d_out;

    const int* src = ei;
    const int* dst = ei + N_EDGES;

    const int SMEM = 2 * 128 * LDH * 2;   // 69632 bytes
    cudaFuncSetAttribute(k_gemm_scatter, cudaFuncAttributeMaxDynamicSharedMemorySize, SMEM);

    k_count<<<(N_EDGES / 4 + 255) / 256, 256>>>(dst);
    k_scan<<<N_SCAN_BLOCKS, SCAN_B>>>();
    k_gemm_scatter<<<GB_BLOCKS, 256, SMEM>>>(x, W, src, dst);
    k_agg<<<(N_NODES + 7) / 8, 256>>>(b, out);
}